// round 6
// baseline (speedup 1.0000x reference)
#include <cuda_runtime.h>
#include <math.h>

#define B_   16
#define C_   384
#define S_   784
#define NH_  6
#define HD_  64
#define NBI  9
#define NPART 256          // 16 batches * 16 spatial tiles
#define NTOK (B_*S_)       // 12544

// ---------------- scratch (static device globals; no allocation) ------------
__device__ float g_dw  [(size_t)NBI*NTOK*C_];   // [bi][b*S+s][c]  dw-conv out
__device__ float g_qkv [(size_t)NBI*NTOK*C_];   // [bi][b][h][s][d] head tensors
__device__ float g_M   [NBI*C_*C_];             // combined lin@pw per branch
__device__ float g_psum[NBI*C_*NPART];
__device__ float g_psq [NBI*C_*NPART];
__device__ float g_a   [NBI*C_];                // BN scale fold
__device__ float g_bc  [NBI*C_];                // BN shift fold
__device__ float g_bias[NBI*C_];                // combined output bias

// ---------------- 1) depthwise 3x3 conv + BN partial stats ------------------
__global__ void dw_kernel(const float* __restrict__ x1, const float* __restrict__ x2,
                          const float* __restrict__ dww) {
    int c    = threadIdx.x;        // 0..383
    int tile = blockIdx.x;         // 16 tiles of 49 spatial positions
    int b    = blockIdx.y;
    int bi   = blockIdx.z;
    int br   = bi / 3;

    float w[9];
#pragma unroll
    for (int k = 0; k < 9; k++) w[k] = dww[(bi*C_ + c)*9 + k];

    const float* X1 = x1 + (size_t)b*S_*C_;
    const float* X2 = x2 + (size_t)b*S_*C_;
    float* out = g_dw + ((size_t)bi*B_ + b)*(size_t)S_*C_;

    float sum = 0.f, sq = 0.f;
    for (int i = 0; i < 49; i++) {
        int s = tile*49 + i;
        int y = s / 28, x = s - y*28;
        float acc = 0.f;
#pragma unroll
        for (int ky = 0; ky < 3; ky++) {
            int yy = y + ky - 1;
            if (yy < 0 || yy >= 28) continue;
#pragma unroll
            for (int kx = 0; kx < 3; kx++) {
                int xx = x + kx - 1;
                if (xx < 0 || xx >= 28) continue;
                int sn = yy*28 + xx;
                float v;
                if      (br == 0) v = X1[sn*C_ + c];
                else if (br == 1) v = X2[sn*C_ + c];
                else              v = X1[sn*C_ + c] + X2[sn*C_ + c];
                acc += w[ky*3+kx] * v;
            }
        }
        out[s*C_ + c] = acc;
        sum += acc;  sq += acc*acc;
    }
    int p = b*16 + tile;
    g_psum[(bi*C_ + c)*NPART + p] = sum;
    g_psq [(bi*C_ + c)*NPART + p] = sq;
}

// ---------------- 2) finalize BN stats (deterministic fixed-order) ----------
__global__ void stats_kernel(const float* __restrict__ gamma, const float* __restrict__ beta) {
    int t = blockIdx.x*blockDim.x + threadIdx.x;
    if (t >= NBI*C_) return;
    double s = 0.0, q = 0.0;
    const float* ps = g_psum + (size_t)t*NPART;
    const float* pq = g_psq  + (size_t)t*NPART;
    for (int i = 0; i < NPART; i++) { s += ps[i]; q += pq[i]; }
    const double N = (double)(B_*S_);
    float mu  = (float)(s / N);
    float var = (float)(q / N - (s/N)*(s/N));
    float a   = gamma[t] * rsqrtf(var + 1e-5f);
    g_a [t] = a;
    g_bc[t] = beta[t] - mu*a;
}

// ---------------- 3) fold: M[bi] = lin[li] @ pw[bi]  (384x384x384, x9) ------
__global__ void __launch_bounds__(256) fold_kernel(const float* __restrict__ pw,
                                                   const float* __restrict__ lin) {
    int bi = blockIdx.z;
    int br = bi / 3, j = bi - 3*br;
    int li = (br == 2 ? 3 : 3*br) + j;      // branch-3 reuses branch-2 lin weights
    const float* L = lin + (size_t)li*C_*C_;   // [o][j]
    const float* P = pw  + (size_t)bi*C_*C_;   // [j][c]

    __shared__ float As[16][65];
    __shared__ float Bs[16][65];
    int t  = threadIdx.x;
    int tx = t & 15, ty = t >> 4;
    int obase = blockIdx.y*64, cbase = blockIdx.x*64;
    float acc[4][4] = {};

    for (int k0 = 0; k0 < C_; k0 += 16) {
#pragma unroll
        for (int e = 0; e < 4; e++) {
            int idx = t + e*256;
            int kk = idx & 15, oo = idx >> 4;
            As[kk][oo] = L[(obase+oo)*C_ + k0 + kk];
        }
#pragma unroll
        for (int e = 0; e < 4; e++) {
            int cc = t & 63, kk = (t >> 6) + e*4;
            Bs[kk][cc] = P[(k0+kk)*C_ + cbase + cc];
        }
        __syncthreads();
#pragma unroll
        for (int kk = 0; kk < 16; kk++) {
            float ar[4], brr[4];
#pragma unroll
            for (int i = 0; i < 4; i++) ar[i]  = As[kk][ty*4+i];
#pragma unroll
            for (int jj = 0; jj < 4; jj++) brr[jj] = Bs[kk][tx*4+jj];
#pragma unroll
            for (int i = 0; i < 4; i++)
#pragma unroll
                for (int jj = 0; jj < 4; jj++) acc[i][jj] += ar[i]*brr[jj];
        }
        __syncthreads();
    }
    float* Mo = g_M + (size_t)bi*C_*C_;
#pragma unroll
    for (int i = 0; i < 4; i++)
#pragma unroll
        for (int jj = 0; jj < 4; jj++)
            Mo[(obase+ty*4+i)*C_ + cbase+tx*4+jj] = acc[i][jj];
}

// ---------------- 4) combined bias: lin@pwb + M@bn_shift --------------------
__global__ void bias_kernel(const float* __restrict__ lin, const float* __restrict__ pwb) {
    int t = blockIdx.x*blockDim.x + threadIdx.x;
    if (t >= NBI*C_) return;
    int bi = t / C_, o = t - bi*C_;
    int br = bi/3, j = bi - 3*br;
    int li = (br == 2 ? 3 : 3*br) + j;
    const float* L    = lin + ((size_t)li*C_ + o)*C_;
    const float* Pb   = pwb + (size_t)bi*C_;
    const float* Mrow = g_M + ((size_t)bi*C_ + o)*C_;
    const float* bc   = g_bc + (size_t)bi*C_;
    float s = 0.f;
    for (int k = 0; k < C_; k++) s += L[k]*Pb[k] + Mrow[k]*bc[k];
    g_bias[t] = s;
}

// ---------------- 5) main GEMM: heads = dw @ (M*a)^T + bias -----------------
// 128x64 tile, BK=16, 256 threads, 8x4 per thread. Writes directly into
// [bi][b][h][s][d] layout (h = o/64, d = o%64; obase multiple of 64 => h fixed).
__global__ void __launch_bounds__(256) gemm_kernel() {
    int bi    = blockIdx.z;
    int rbase = blockIdx.y*128;
    int obase = blockIdx.x*64;
    const float* A  = g_dw + (size_t)bi*NTOK*C_;
    const float* Mo = g_M  + (size_t)bi*C_*C_;
    const float* av = g_a  + (size_t)bi*C_;

    __shared__ float As[16][129];
    __shared__ float Bs[16][65];
    int t  = threadIdx.x;
    int tx = t & 15, ty = t >> 4;
    float acc[8][4] = {};

    for (int k0 = 0; k0 < C_; k0 += 16) {
#pragma unroll
        for (int e = 0; e < 8; e++) {
            int idx = t + e*256;
            int kk = idx & 15, mm = idx >> 4;
            As[kk][mm] = A[(size_t)(rbase+mm)*C_ + k0+kk];
        }
#pragma unroll
        for (int e = 0; e < 4; e++) {
            int idx = t + e*256;
            int kk = idx & 15, nn = idx >> 4;
            Bs[kk][nn] = Mo[(obase+nn)*C_ + k0+kk] * av[k0+kk];  // BN scale fold
        }
        __syncthreads();
#pragma unroll
        for (int kk = 0; kk < 16; kk++) {
            float ar[8], brr[4];
#pragma unroll
            for (int i = 0; i < 8; i++) ar[i]  = As[kk][ty*8+i];
#pragma unroll
            for (int jj = 0; jj < 4; jj++) brr[jj] = Bs[kk][tx*4+jj];
#pragma unroll
            for (int i = 0; i < 8; i++)
#pragma unroll
                for (int jj = 0; jj < 4; jj++) acc[i][jj] += ar[i]*brr[jj];
        }
        __syncthreads();
    }

    int h = obase >> 6;
    const float* bias = g_bias + (size_t)bi*C_;
#pragma unroll
    for (int i = 0; i < 8; i++) {
        int r = rbase + ty*8 + i;
        int b = r / S_, s = r - b*S_;
        float* dst = g_qkv + ((((size_t)bi*B_ + b)*NH_ + h)*S_ + s)*HD_;
#pragma unroll
        for (int jj = 0; jj < 4; jj++) {
            int o = obase + tx*4 + jj;
            dst[tx*4+jj] = acc[i][jj] + bias[o];
        }
    }
}

// ---------------- 6) flash attention, TQ=64 / TK=32 -------------------------
__global__ void __launch_bounds__(256) attn_kernel(float* __restrict__ out) {
    int qt = blockIdx.x;            // 13 q-tiles of 64 (last partial)
    int bh = blockIdx.y;            // b*NH + h
    int br = blockIdx.z;
    int b = bh / NH_, h = bh - b*NH_;

    const float* Qp = g_qkv + (((size_t)(3*br+0)*B_ + b)*NH_ + h)*(size_t)S_*HD_;
    const float* Kp = g_qkv + (((size_t)(3*br+1)*B_ + b)*NH_ + h)*(size_t)S_*HD_;
    const float* Vp = g_qkv + (((size_t)(3*br+2)*B_ + b)*NH_ + h)*(size_t)S_*HD_;
    // raw (b,h,t,d)->(b,t,h*d) reshape: out offset = b*S*C + h*S*64 + t*64 + d
    float* Op = out + ((size_t)br*B_ + b)*(size_t)S_*C_ + (size_t)h*S_*HD_;

    __shared__ float Qs[64][65];
    __shared__ float Ks[32][65];
    __shared__ float Vs[32][65];
    __shared__ float Ps[64][33];

    int t  = threadIdx.x;
    int tx = t & 15, ty = t >> 4;
    int q0 = qt*64;

#pragma unroll
    for (int e = 0; e < 16; e++) {
        int idx = t + e*256;
        int r = idx >> 6, d = idx & 63;
        int q = q0 + r;
        Qs[r][d] = (q < S_) ? Qp[(size_t)q*HD_ + d] : 0.f;
    }

    float m[4], l[4], O[4][4];
#pragma unroll
    for (int i = 0; i < 4; i++) {
        m[i] = -1e30f; l[i] = 0.f;
#pragma unroll
        for (int jj = 0; jj < 4; jj++) O[i][jj] = 0.f;
    }

    const float scale = 0.05103103630798288f;   // 384^-0.5

    for (int kt = 0; kt < 25; kt++) {
        int k0 = kt*32;
        __syncthreads();     // prev PV done (and Qs ready on first iter)
#pragma unroll
        for (int e = 0; e < 8; e++) {
            int idx = t + e*256;
            int r = idx >> 6, d = idx & 63;
            int kg = k0 + r;
            bool ok = (kg < S_);
            Ks[r][d] = ok ? Kp[(size_t)kg*HD_ + d] : 0.f;
            Vs[r][d] = ok ? Vp[(size_t)kg*HD_ + d] : 0.f;
        }
        __syncthreads();

        float sc[4][2] = {};
#pragma unroll
        for (int d = 0; d < 64; d++) {
            float qr[4];
#pragma unroll
            for (int i = 0; i < 4; i++) qr[i] = Qs[ty*4+i][d];
            float ka = Ks[tx*2][d], kb = Ks[tx*2+1][d];
#pragma unroll
            for (int i = 0; i < 4; i++) { sc[i][0] += qr[i]*ka; sc[i][1] += qr[i]*kb; }
        }
        bool v0 = (k0 + tx*2    ) < S_;
        bool v1 = (k0 + tx*2 + 1) < S_;
#pragma unroll
        for (int i = 0; i < 4; i++) {
            sc[i][0] = v0 ? sc[i][0]*scale : -1e30f;
            sc[i][1] = v1 ? sc[i][1]*scale : -1e30f;
        }
#pragma unroll
        for (int i = 0; i < 4; i++) {
            float tm = fmaxf(sc[i][0], sc[i][1]);
#pragma unroll
            for (int off = 8; off > 0; off >>= 1)
                tm = fmaxf(tm, __shfl_xor_sync(0xffffffffu, tm, off));
            float mn    = fmaxf(m[i], tm);
            float alpha = __expf(m[i] - mn);
            float p0    = __expf(sc[i][0] - mn);
            float p1    = __expf(sc[i][1] - mn);
            float rs = p0 + p1;
#pragma unroll
            for (int off = 8; off > 0; off >>= 1)
                rs += __shfl_xor_sync(0xffffffffu, rs, off);
            l[i] = l[i]*alpha + rs;
            m[i] = mn;
#pragma unroll
            for (int jj = 0; jj < 4; jj++) O[i][jj] *= alpha;
            Ps[ty*4+i][tx*2]   = p0;
            Ps[ty*4+i][tx*2+1] = p1;
        }
        __syncthreads();
#pragma unroll 8
        for (int kk = 0; kk < 32; kk++) {
            float pr[4], vr[4];
#pragma unroll
            for (int i = 0; i < 4; i++) pr[i] = Ps[ty*4+i][kk];
#pragma unroll
            for (int jj = 0; jj < 4; jj++) vr[jj] = Vs[kk][tx*4+jj];
#pragma unroll
            for (int i = 0; i < 4; i++)
#pragma unroll
                for (int jj = 0; jj < 4; jj++) O[i][jj] += pr[i]*vr[jj];
        }
    }

#pragma unroll
    for (int i = 0; i < 4; i++) {
        int q = q0 + ty*4 + i;
        if (q < S_) {
            float inv = 1.0f / l[i];
#pragma unroll
            for (int jj = 0; jj < 4; jj++)
                Op[(size_t)q*HD_ + tx*4 + jj] = O[i][jj]*inv;
        }
    }
}

// ---------------------------------------------------------------------------
extern "C" void kernel_launch(void* const* d_in, const int* in_sizes, int n_in,
                              void* d_out, int out_size) {
    // metadata order: x1, h1, w1, x2, h2, w2, dw_w, bn_gamma, bn_beta, pw_w, pw_b, lin_w
    const float* x1  = (const float*)d_in[0];
    const float* x2  = (const float*)d_in[3];
    const float* dww = (const float*)d_in[6];
    const float* gam = (const float*)d_in[7];
    const float* bet = (const float*)d_in[8];
    const float* pw  = (const float*)d_in[9];
    const float* pwb = (const float*)d_in[10];
    const float* lin = (const float*)d_in[11];
    float* out = (float*)d_out;

    dw_kernel  <<<dim3(16, 16, 9), 384>>>(x1, x2, dww);
    stats_kernel<<<(NBI*C_ + 255)/256, 256>>>(gam, bet);
    fold_kernel<<<dim3(6, 6, 9), 256>>>(pw, lin);
    bias_kernel<<<(NBI*C_ + 255)/256, 256>>>(lin, pwb);
    gemm_kernel<<<dim3(6, 98, 9), 256>>>();
    attn_kernel<<<dim3(13, 96, 3), 256>>>(out);
}

// round 7
// speedup vs baseline: 1.3739x; 1.3739x over previous
#include <cuda_runtime.h>
#include <math.h>
#include <stdint.h>

#define B_   16
#define C_   384
#define S_   784
#define NH_  6
#define HD_  64
#define NBI  9
#define NPART 256          // 16 batches * 16 spatial tiles
#define NTOK (B_*S_)       // 12544

// ---------------- scratch (static device globals; no allocation) ------------
__device__ float g_dw  [(size_t)NBI*NTOK*C_];   // [bi][b*S+s][c]  dw-conv out
__device__ float g_qkv [(size_t)NBI*NTOK*C_];   // [bi][b][h][s][d] head tensors
__device__ float g_M   [NBI*C_*C_];             // combined lin@pw per branch
__device__ float g_psum[NBI*C_*NPART];
__device__ float g_psq [NBI*C_*NPART];
__device__ float g_a   [NBI*C_];                // BN scale fold
__device__ float g_bc  [NBI*C_];                // BN shift fold
__device__ float g_bias[NBI*C_];                // combined output bias

// ---------------- helpers ---------------------------------------------------
__device__ __forceinline__ uint32_t cvt_tf32(float x) {
    uint32_t r;
    asm("cvt.rna.tf32.f32 %0, %1;" : "=r"(r) : "f"(x));
    return r;
}

__device__ __forceinline__ void mma_tf32(float c[4], const uint32_t a[4],
                                         uint32_t b0, uint32_t b1) {
    asm volatile(
        "mma.sync.aligned.m16n8k8.row.col.f32.tf32.tf32.f32 "
        "{%0,%1,%2,%3}, {%4,%5,%6,%7}, {%8,%9}, {%0,%1,%2,%3};\n"
        : "+f"(c[0]), "+f"(c[1]), "+f"(c[2]), "+f"(c[3])
        : "r"(a[0]), "r"(a[1]), "r"(a[2]), "r"(a[3]), "r"(b0), "r"(b1));
}

// ---------------- 1) depthwise 3x3 conv + BN partial stats ------------------
__global__ void dw_kernel(const float* __restrict__ x1, const float* __restrict__ x2,
                          const float* __restrict__ dww) {
    int c    = threadIdx.x;        // 0..383
    int tile = blockIdx.x;         // 16 tiles of 49 spatial positions
    int b    = blockIdx.y;
    int bi   = blockIdx.z;
    int br   = bi / 3;

    float w[9];
#pragma unroll
    for (int k = 0; k < 9; k++) w[k] = dww[(bi*C_ + c)*9 + k];

    const float* X1 = x1 + (size_t)b*S_*C_;
    const float* X2 = x2 + (size_t)b*S_*C_;
    float* out = g_dw + ((size_t)bi*B_ + b)*(size_t)S_*C_;

    float sum = 0.f, sq = 0.f;
    for (int i = 0; i < 49; i++) {
        int s = tile*49 + i;
        int y = s / 28, x = s - y*28;
        float acc = 0.f;
#pragma unroll
        for (int ky = 0; ky < 3; ky++) {
            int yy = y + ky - 1;
            if (yy < 0 || yy >= 28) continue;
#pragma unroll
            for (int kx = 0; kx < 3; kx++) {
                int xx = x + kx - 1;
                if (xx < 0 || xx >= 28) continue;
                int sn = yy*28 + xx;
                float v;
                if      (br == 0) v = X1[sn*C_ + c];
                else if (br == 1) v = X2[sn*C_ + c];
                else              v = X1[sn*C_ + c] + X2[sn*C_ + c];
                acc += w[ky*3+kx] * v;
            }
        }
        out[s*C_ + c] = acc;
        sum += acc;  sq += acc*acc;
    }
    int p = b*16 + tile;
    g_psum[(bi*C_ + c)*NPART + p] = sum;
    g_psq [(bi*C_ + c)*NPART + p] = sq;
}

// ---------------- 2) finalize BN stats (warp per channel) -------------------
__global__ void stats_kernel(const float* __restrict__ gamma, const float* __restrict__ beta) {
    int gw   = (blockIdx.x*256 + threadIdx.x) >> 5;
    int lane = threadIdx.x & 31;
    if (gw >= NBI*C_) return;
    const float* ps = g_psum + (size_t)gw*NPART;
    const float* pq = g_psq  + (size_t)gw*NPART;
    double s = 0.0, q = 0.0;
#pragma unroll
    for (int i = 0; i < NPART/32; i++) { s += ps[lane + i*32]; q += pq[lane + i*32]; }
#pragma unroll
    for (int o = 16; o > 0; o >>= 1) {
        s += __shfl_xor_sync(0xffffffffu, s, o);
        q += __shfl_xor_sync(0xffffffffu, q, o);
    }
    if (lane == 0) {
        const double N = (double)(B_*S_);
        float mu  = (float)(s / N);
        float var = (float)(q / N - (s/N)*(s/N));
        float a   = gamma[gw] * rsqrtf(var + 1e-5f);
        g_a [gw] = a;
        g_bc[gw] = beta[gw] - mu*a;
    }
}

// ---------------- 3) fold: M[bi] = lin[li] @ pw[bi]  (384x384x384, x9) ------
__global__ void __launch_bounds__(256) fold_kernel(const float* __restrict__ pw,
                                                   const float* __restrict__ lin) {
    int bi = blockIdx.z;
    int br = bi / 3, j = bi - 3*br;
    int li = (br == 2 ? 3 : 3*br) + j;      // branch-3 reuses branch-2 lin weights
    const float* L = lin + (size_t)li*C_*C_;   // [o][j]
    const float* P = pw  + (size_t)bi*C_*C_;   // [j][c]

    __shared__ float As[16][65];
    __shared__ float Bs[16][65];
    int t  = threadIdx.x;
    int tx = t & 15, ty = t >> 4;
    int obase = blockIdx.y*64, cbase = blockIdx.x*64;
    float acc[4][4] = {};

    for (int k0 = 0; k0 < C_; k0 += 16) {
#pragma unroll
        for (int e = 0; e < 4; e++) {
            int idx = t + e*256;
            int kk = idx & 15, oo = idx >> 4;
            As[kk][oo] = L[(obase+oo)*C_ + k0 + kk];
        }
#pragma unroll
        for (int e = 0; e < 4; e++) {
            int cc = t & 63, kk = (t >> 6) + e*4;
            Bs[kk][cc] = P[(k0+kk)*C_ + cbase + cc];
        }
        __syncthreads();
#pragma unroll
        for (int kk = 0; kk < 16; kk++) {
            float ar[4], brr[4];
#pragma unroll
            for (int i = 0; i < 4; i++) ar[i]  = As[kk][ty*4+i];
#pragma unroll
            for (int jj = 0; jj < 4; jj++) brr[jj] = Bs[kk][tx*4+jj];
#pragma unroll
            for (int i = 0; i < 4; i++)
#pragma unroll
                for (int jj = 0; jj < 4; jj++) acc[i][jj] += ar[i]*brr[jj];
        }
        __syncthreads();
    }
    float* Mo = g_M + (size_t)bi*C_*C_;
#pragma unroll
    for (int i = 0; i < 4; i++)
#pragma unroll
        for (int jj = 0; jj < 4; jj++)
            Mo[(obase+ty*4+i)*C_ + cbase+tx*4+jj] = acc[i][jj];
}

// ---------------- 4) combined bias (warp per output) ------------------------
__global__ void bias_kernel(const float* __restrict__ lin, const float* __restrict__ pwb) {
    int gw   = (blockIdx.x*256 + threadIdx.x) >> 5;
    int lane = threadIdx.x & 31;
    if (gw >= NBI*C_) return;
    int bi = gw / C_, o = gw - bi*C_;
    int brr = bi/3, j = bi - 3*brr;
    int li = (brr == 2 ? 3 : 3*brr) + j;
    const float* L    = lin + ((size_t)li*C_ + o)*C_;
    const float* Pb   = pwb + (size_t)bi*C_;
    const float* Mrow = g_M + ((size_t)bi*C_ + o)*C_;
    const float* bc   = g_bc + (size_t)bi*C_;
    float s = 0.f;
    for (int k = lane; k < C_; k += 32) s += L[k]*Pb[k] + Mrow[k]*bc[k];
#pragma unroll
    for (int off = 16; off > 0; off >>= 1) s += __shfl_xor_sync(0xffffffffu, s, off);
    if (lane == 0) g_bias[gw] = s;
}

// ---------------- 5) main GEMM (tf32 tensor cores) --------------------------
// heads = dw @ (M*a)^T + bias. Block tile 128x128, BK=32, 256 thr = 8 warps
// (4m x 2n), warp tile 32x64, mma.m16n8k8.tf32. Writes [bi][b][h][s][d].
__global__ void __launch_bounds__(256) gemm_kernel() {
    __shared__ uint32_t As[128][36];   // [r][k] tf32 bits (pad 36: conflict-free frags)
    __shared__ uint32_t Bs[128][36];   // [o][k] tf32 bits (M*a)

    int bi    = blockIdx.z;
    int rbase = blockIdx.y * 128;
    int obase = blockIdx.x * 128;
    const float* A  = g_dw + (size_t)bi*NTOK*C_;
    const float* Mo = g_M  + (size_t)bi*C_*C_;
    const float* av = g_a  + (size_t)bi*C_;

    int t    = threadIdx.x;
    int wid  = t >> 5, lane = t & 31;
    int wm   = wid >> 1, wn = wid & 1;   // warp grid 4x2
    int lr   = lane >> 2, lc = lane & 3;

    float acc[2][8][4] = {};

    for (int k0 = 0; k0 < C_; k0 += 32) {
        __syncthreads();
#pragma unroll
        for (int e = 0; e < 16; e++) {
            int idx = e*256 + t;
            int r = idx >> 5, kk = idx & 31;
            As[r][kk] = cvt_tf32(A[(size_t)(rbase+r)*C_ + k0 + kk]);
        }
#pragma unroll
        for (int e = 0; e < 16; e++) {
            int idx = e*256 + t;
            int n = idx >> 5, kk = idx & 31;
            Bs[n][kk] = cvt_tf32(Mo[(size_t)(obase+n)*C_ + k0 + kk] * av[k0+kk]);
        }
        __syncthreads();
#pragma unroll
        for (int ks = 0; ks < 32; ks += 8) {
            uint32_t af[2][4];
#pragma unroll
            for (int i = 0; i < 2; i++) {
                int r = wm*32 + i*16;
                af[i][0] = As[r + lr    ][ks + lc    ];
                af[i][1] = As[r + lr + 8][ks + lc    ];
                af[i][2] = As[r + lr    ][ks + lc + 4];
                af[i][3] = As[r + lr + 8][ks + lc + 4];
            }
#pragma unroll
            for (int j = 0; j < 8; j++) {
                int n = wn*64 + j*8;
                uint32_t b0 = Bs[n + lr][ks + lc    ];
                uint32_t b1 = Bs[n + lr][ks + lc + 4];
#pragma unroll
                for (int i = 0; i < 2; i++) mma_tf32(acc[i][j], af[i], b0, b1);
            }
        }
    }

    // epilogue: D frag: c0(r, 2lc) c1(r, 2lc+1) c2(r+8, 2lc) c3(r+8, 2lc+1)
    const float* bias = g_bias + (size_t)bi*C_;
#pragma unroll
    for (int i = 0; i < 2; i++) {
        int r0 = rbase + wm*32 + i*16 + lr;
        int r1 = r0 + 8;
        int b0r = r0 / S_, s0r = r0 - b0r*S_;
        int b1r = r1 / S_, s1r = r1 - b1r*S_;
#pragma unroll
        for (int j = 0; j < 8; j++) {
            int o = obase + wn*64 + j*8 + 2*lc;
            int h = o >> 6, d = o & 63;
            float bo0 = bias[o], bo1 = bias[o+1];
            float* d0 = g_qkv + ((((size_t)bi*B_ + b0r)*NH_ + h)*S_ + s0r)*HD_ + d;
            d0[0] = acc[i][j][0] + bo0;
            d0[1] = acc[i][j][1] + bo1;
            float* d1 = g_qkv + ((((size_t)bi*B_ + b1r)*NH_ + h)*S_ + s1r)*HD_ + d;
            d1[0] = acc[i][j][2] + bo0;
            d1[1] = acc[i][j][3] + bo1;
        }
    }
}

// ---------------- 6) flash attention, TQ=64 / TK=64, vectorized LDS ---------
// Smem: Qt = Q^T [d][q] (group-swizzled), KP = K^T [d][k] then P [k][q]
// (overlaid), Vs = V [k][d]. 48KB exactly. 256 thr as 16(tx,k/d)x16(ty,q),
// 4x4 register tiles in both score and PV phases; all smem reads are LDS.128.
__global__ void __launch_bounds__(256) attn_kernel(float* __restrict__ out) {
    __shared__ float Qt[64][64];
    __shared__ float KP[64][64];
    __shared__ float Vs[64][64];

    int t  = threadIdx.x;
    int tx = t & 15, ty = t >> 4;
    int qt = blockIdx.x;            // 13 q-tiles of 64
    int bh = blockIdx.y;            // b*NH + h
    int br = blockIdx.z;
    int b = bh / NH_, h = bh - b*NH_;

    const float* Qp = g_qkv + (((size_t)(3*br+0)*B_ + b)*NH_ + h)*(size_t)S_*HD_;
    const float* Kp = g_qkv + (((size_t)(3*br+1)*B_ + b)*NH_ + h)*(size_t)S_*HD_;
    const float* Vp = g_qkv + (((size_t)(3*br+2)*B_ + b)*NH_ + h)*(size_t)S_*HD_;
    // raw (b,h,t,d)->(b,t,h*d) reshape: out offset = b*S*C + h*S*64 + t*64 + d
    float* Op = out + ((size_t)br*B_ + b)*(size_t)S_*C_ + (size_t)h*S_*HD_;

    int q0 = qt*64;

    // Q load (gmem coalesced) -> transposed + group-swizzled smem
#pragma unroll
    for (int e = 0; e < 16; e++) {
        int idx = e*256 + t;
        int dd = idx & 63, q = idx >> 6;
        float v = (q0 + q < S_) ? Qp[(size_t)(q0+q)*HD_ + dd] : 0.f;
        Qt[dd][((((q >> 2) + dd) & 15) << 2) + (q & 3)] = v;
    }

    float m[4], l[4], O[4][4];
#pragma unroll
    for (int i = 0; i < 4; i++) {
        m[i] = -1e30f; l[i] = 0.f;
#pragma unroll
        for (int j = 0; j < 4; j++) O[i][j] = 0.f;
    }

    const float scale = 0.05103103630798288f;   // 384^-0.5

    for (int kt = 0; kt < 13; kt++) {
        int k0 = kt*64;
        __syncthreads();     // prev PV done reading KP/Vs (also first-iter Qt fence below)
#pragma unroll
        for (int e = 0; e < 16; e++) {
            int idx = e*256 + t;
            int dd = idx & 63, k = idx >> 6;
            bool ok = (k0 + k) < S_;
            KP[dd][((((k >> 2) + dd) & 15) << 2) + (k & 3)] =
                ok ? Kp[(size_t)(k0+k)*HD_ + dd] : 0.f;
            Vs[k][dd] = ok ? Vp[(size_t)(k0+k)*HD_ + dd] : 0.f;
        }
        __syncthreads();

        // ---- scores: s[4q][4k] = Q.K^T ----
        float s[4][4] = {};
#pragma unroll 8
        for (int d = 0; d < 64; d++) {
            float4 qv = *(const float4*)&Qt[d][((ty + d) & 15) << 2];
            float4 kv = *(const float4*)&KP[d][((tx + d) & 15) << 2];
            s[0][0] += qv.x*kv.x; s[0][1] += qv.x*kv.y; s[0][2] += qv.x*kv.z; s[0][3] += qv.x*kv.w;
            s[1][0] += qv.y*kv.x; s[1][1] += qv.y*kv.y; s[1][2] += qv.y*kv.z; s[1][3] += qv.y*kv.w;
            s[2][0] += qv.z*kv.x; s[2][1] += qv.z*kv.y; s[2][2] += qv.z*kv.z; s[2][3] += qv.z*kv.w;
            s[3][0] += qv.w*kv.x; s[3][1] += qv.w*kv.y; s[3][2] += qv.w*kv.z; s[3][3] += qv.w*kv.w;
        }

        int kbase = k0 + 4*tx;
#pragma unroll
        for (int j = 0; j < 4; j++) {
            bool v = (kbase + j) < S_;
#pragma unroll
            for (int i = 0; i < 4; i++)
                s[i][j] = v ? s[i][j]*scale : -1e30f;
        }

        // ---- online softmax (row reduce across tx via shuffle) ----
        float p[4][4];
#pragma unroll
        for (int i = 0; i < 4; i++) {
            float mx = fmaxf(fmaxf(s[i][0], s[i][1]), fmaxf(s[i][2], s[i][3]));
#pragma unroll
            for (int o_ = 8; o_ > 0; o_ >>= 1)
                mx = fmaxf(mx, __shfl_xor_sync(0xffffffffu, mx, o_));
            float mn    = fmaxf(m[i], mx);
            float alpha = __expf(m[i] - mn);
            float rs = 0.f;
#pragma unroll
            for (int j = 0; j < 4; j++) { p[i][j] = __expf(s[i][j] - mn); rs += p[i][j]; }
#pragma unroll
            for (int o_ = 8; o_ > 0; o_ >>= 1)
                rs += __shfl_xor_sync(0xffffffffu, rs, o_);
            l[i] = l[i]*alpha + rs;
            m[i] = mn;
#pragma unroll
            for (int j = 0; j < 4; j++) O[i][j] *= alpha;
        }

        __syncthreads();   // all score reads of KP done
        // write P into KP as [k][q] (group-swizzled on q)
#pragma unroll
        for (int j = 0; j < 4; j++) {
            int k   = 4*tx + j;
            int col = ((ty + k) & 15) << 2;
#pragma unroll
            for (int i = 0; i < 4; i++)
                KP[k][col + i] = p[i][j];
        }
        __syncthreads();

        // ---- PV: O[4q][4d] += P.V ----
#pragma unroll 8
        for (int k = 0; k < 64; k++) {
            float4 pv = *(const float4*)&KP[k][((ty + k) & 15) << 2];
            float4 vv = *(const float4*)&Vs[k][tx << 2];
            O[0][0] += pv.x*vv.x; O[0][1] += pv.x*vv.y; O[0][2] += pv.x*vv.z; O[0][3] += pv.x*vv.w;
            O[1][0] += pv.y*vv.x; O[1][1] += pv.y*vv.y; O[1][2] += pv.y*vv.z; O[1][3] += pv.y*vv.w;
            O[2][0] += pv.z*vv.x; O[2][1] += pv.z*vv.y; O[2][2] += pv.z*vv.z; O[2][3] += pv.z*vv.w;
            O[3][0] += pv.w*vv.x; O[3][1] += pv.w*vv.y; O[3][2] += pv.w*vv.z; O[3][3] += pv.w*vv.w;
        }
    }

#pragma unroll
    for (int i = 0; i < 4; i++) {
        int q = q0 + 4*ty + i;
        if (q < S_) {
            float inv = 1.0f / l[i];
            float4 o4 = make_float4(O[i][0]*inv, O[i][1]*inv, O[i][2]*inv, O[i][3]*inv);
            *(float4*)&Op[(size_t)q*HD_ + (tx << 2)] = o4;
        }
    }
}

// ---------------------------------------------------------------------------
extern "C" void kernel_launch(void* const* d_in, const int* in_sizes, int n_in,
                              void* d_out, int out_size) {
    // metadata order: x1, h1, w1, x2, h2, w2, dw_w, bn_gamma, bn_beta, pw_w, pw_b, lin_w
    const float* x1  = (const float*)d_in[0];
    const float* x2  = (const float*)d_in[3];
    const float* dww = (const float*)d_in[6];
    const float* gam = (const float*)d_in[7];
    const float* bet = (const float*)d_in[8];
    const float* pw  = (const float*)d_in[9];
    const float* pwb = (const float*)d_in[10];
    const float* lin = (const float*)d_in[11];
    float* out = (float*)d_out;

    dw_kernel   <<<dim3(16, 16, 9), 384>>>(x1, x2, dww);
    stats_kernel<<<(NBI*C_*32 + 255)/256, 256>>>(gam, bet);
    fold_kernel <<<dim3(6, 6, 9), 256>>>(pw, lin);
    bias_kernel <<<(NBI*C_*32 + 255)/256, 256>>>(lin, pwb);
    gemm_kernel <<<dim3(3, 98, 9), 256>>>();
    attn_kernel <<<dim3(13, 96, 3), 256>>>(out);
}

// round 8
// speedup vs baseline: 1.7612x; 1.2819x over previous
#include <cuda_runtime.h>
#include <math.h>
#include <stdint.h>

#define B_   16
#define C_   384
#define S_   784
#define NH_  6
#define HD_  64
#define NBI  9
#define NPART 256          // 16 batches * 16 spatial tiles
#define NTOK (B_*S_)       // 12544

// ---------------- scratch (static device globals; no allocation) ------------
__device__ float g_dw  [(size_t)NBI*NTOK*C_];   // [bi][b*S+s][c]  dw-conv out
__device__ float g_qkv [(size_t)NBI*NTOK*C_];   // [bi][b][h][s][d] head tensors
__device__ float g_M   [NBI*C_*C_];             // combined lin@pw per branch
__device__ float g_psum[NBI*C_*NPART];
__device__ float g_psq [NBI*C_*NPART];
__device__ float g_a   [NBI*C_];                // BN scale fold
__device__ float g_bc  [NBI*C_];                // BN shift fold
__device__ float g_bias[NBI*C_];                // combined output bias

// ---------------- helpers ---------------------------------------------------
__device__ __forceinline__ uint32_t cvt_tf32(float x) {
    uint32_t r;
    asm("cvt.rna.tf32.f32 %0, %1;" : "=r"(r) : "f"(x));
    return r;
}

__device__ __forceinline__ void mma_tf32(float c[4], const uint32_t a[4],
                                         uint32_t b0, uint32_t b1) {
    asm volatile(
        "mma.sync.aligned.m16n8k8.row.col.f32.tf32.tf32.f32 "
        "{%0,%1,%2,%3}, {%4,%5,%6,%7}, {%8,%9}, {%0,%1,%2,%3};\n"
        : "+f"(c[0]), "+f"(c[1]), "+f"(c[2]), "+f"(c[3])
        : "r"(a[0]), "r"(a[1]), "r"(a[2]), "r"(a[3]), "r"(b0), "r"(b1));
}

// ---------------- 1) depthwise 3x3 conv + BN partial stats ------------------
__global__ void dw_kernel(const float* __restrict__ x1, const float* __restrict__ x2,
                          const float* __restrict__ dww) {
    int c    = threadIdx.x;        // 0..383
    int tile = blockIdx.x;         // 16 tiles of 49 spatial positions
    int b    = blockIdx.y;
    int bi   = blockIdx.z;
    int br   = bi / 3;

    float w[9];
#pragma unroll
    for (int k = 0; k < 9; k++) w[k] = dww[(bi*C_ + c)*9 + k];

    const float* X1 = x1 + (size_t)b*S_*C_;
    const float* X2 = x2 + (size_t)b*S_*C_;
    float* out = g_dw + ((size_t)bi*B_ + b)*(size_t)S_*C_;

    float sum = 0.f, sq = 0.f;
    for (int i = 0; i < 49; i++) {
        int s = tile*49 + i;
        int y = s / 28, x = s - y*28;
        float acc = 0.f;
#pragma unroll
        for (int ky = 0; ky < 3; ky++) {
            int yy = y + ky - 1;
            if (yy < 0 || yy >= 28) continue;
#pragma unroll
            for (int kx = 0; kx < 3; kx++) {
                int xx = x + kx - 1;
                if (xx < 0 || xx >= 28) continue;
                int sn = yy*28 + xx;
                float v;
                if      (br == 0) v = X1[sn*C_ + c];
                else if (br == 1) v = X2[sn*C_ + c];
                else              v = X1[sn*C_ + c] + X2[sn*C_ + c];
                acc += w[ky*3+kx] * v;
            }
        }
        out[s*C_ + c] = acc;
        sum += acc;  sq += acc*acc;
    }
    int p = b*16 + tile;
    g_psum[(bi*C_ + c)*NPART + p] = sum;
    g_psq [(bi*C_ + c)*NPART + p] = sq;
}

// ---------------- 2) finalize BN stats (warp per channel) -------------------
__global__ void stats_kernel(const float* __restrict__ gamma, const float* __restrict__ beta) {
    int gw   = (blockIdx.x*256 + threadIdx.x) >> 5;
    int lane = threadIdx.x & 31;
    if (gw >= NBI*C_) return;
    const float* ps = g_psum + (size_t)gw*NPART;
    const float* pq = g_psq  + (size_t)gw*NPART;
    double s = 0.0, q = 0.0;
#pragma unroll
    for (int i = 0; i < NPART/32; i++) { s += ps[lane + i*32]; q += pq[lane + i*32]; }
#pragma unroll
    for (int o = 16; o > 0; o >>= 1) {
        s += __shfl_xor_sync(0xffffffffu, s, o);
        q += __shfl_xor_sync(0xffffffffu, q, o);
    }
    if (lane == 0) {
        const double N = (double)(B_*S_);
        float mu  = (float)(s / N);
        float var = (float)(q / N - (s/N)*(s/N));
        float a   = gamma[gw] * rsqrtf(var + 1e-5f);
        g_a [gw] = a;
        g_bc[gw] = beta[gw] - mu*a;
    }
}

// ---------------- 3) fold: M[bi] = lin[li] @ pw[bi]  (384x384x384, x9) ------
__global__ void __launch_bounds__(256) fold_kernel(const float* __restrict__ pw,
                                                   const float* __restrict__ lin) {
    int bi = blockIdx.z;
    int br = bi / 3, j = bi - 3*br;
    int li = (br == 2 ? 3 : 3*br) + j;      // branch-3 reuses branch-2 lin weights
    const float* L = lin + (size_t)li*C_*C_;   // [o][j]
    const float* P = pw  + (size_t)bi*C_*C_;   // [j][c]

    __shared__ float As[16][65];
    __shared__ float Bs[16][65];
    int t  = threadIdx.x;
    int tx = t & 15, ty = t >> 4;
    int obase = blockIdx.y*64, cbase = blockIdx.x*64;
    float acc[4][4] = {};

    for (int k0 = 0; k0 < C_; k0 += 16) {
#pragma unroll
        for (int e = 0; e < 4; e++) {
            int idx = t + e*256;
            int kk = idx & 15, oo = idx >> 4;
            As[kk][oo] = L[(obase+oo)*C_ + k0 + kk];
        }
#pragma unroll
        for (int e = 0; e < 4; e++) {
            int cc = t & 63, kk = (t >> 6) + e*4;
            Bs[kk][cc] = P[(k0+kk)*C_ + cbase + cc];
        }
        __syncthreads();
#pragma unroll
        for (int kk = 0; kk < 16; kk++) {
            float ar[4], brr[4];
#pragma unroll
            for (int i = 0; i < 4; i++) ar[i]  = As[kk][ty*4+i];
#pragma unroll
            for (int jj = 0; jj < 4; jj++) brr[jj] = Bs[kk][tx*4+jj];
#pragma unroll
            for (int i = 0; i < 4; i++)
#pragma unroll
                for (int jj = 0; jj < 4; jj++) acc[i][jj] += ar[i]*brr[jj];
        }
        __syncthreads();
    }
    float* Mo = g_M + (size_t)bi*C_*C_;
#pragma unroll
    for (int i = 0; i < 4; i++)
#pragma unroll
        for (int jj = 0; jj < 4; jj++)
            Mo[(obase+ty*4+i)*C_ + cbase+tx*4+jj] = acc[i][jj];
}

// ---------------- 4) combined bias (warp per output) ------------------------
__global__ void bias_kernel(const float* __restrict__ lin, const float* __restrict__ pwb) {
    int gw   = (blockIdx.x*256 + threadIdx.x) >> 5;
    int lane = threadIdx.x & 31;
    if (gw >= NBI*C_) return;
    int bi = gw / C_, o = gw - bi*C_;
    int brr = bi/3, j = bi - 3*brr;
    int li = (brr == 2 ? 3 : 3*brr) + j;
    const float* L    = lin + ((size_t)li*C_ + o)*C_;
    const float* Pb   = pwb + (size_t)bi*C_;
    const float* Mrow = g_M + ((size_t)bi*C_ + o)*C_;
    const float* bc   = g_bc + (size_t)bi*C_;
    float s = 0.f;
    for (int k = lane; k < C_; k += 32) s += L[k]*Pb[k] + Mrow[k]*bc[k];
#pragma unroll
    for (int off = 16; off > 0; off >>= 1) s += __shfl_xor_sync(0xffffffffu, s, off);
    if (lane == 0) g_bias[gw] = s;
}

// ---------------- 5) main GEMM (tf32 tensor cores) --------------------------
__global__ void __launch_bounds__(256) gemm_kernel() {
    __shared__ uint32_t As[128][36];
    __shared__ uint32_t Bs[128][36];

    int bi    = blockIdx.z;
    int rbase = blockIdx.y * 128;
    int obase = blockIdx.x * 128;
    const float* A  = g_dw + (size_t)bi*NTOK*C_;
    const float* Mo = g_M  + (size_t)bi*C_*C_;
    const float* av = g_a  + (size_t)bi*C_;

    int t    = threadIdx.x;
    int wid  = t >> 5, lane = t & 31;
    int wm   = wid >> 1, wn = wid & 1;
    int lr   = lane >> 2, lc = lane & 3;

    float acc[2][8][4] = {};

    for (int k0 = 0; k0 < C_; k0 += 32) {
        __syncthreads();
#pragma unroll
        for (int e = 0; e < 16; e++) {
            int idx = e*256 + t;
            int r = idx >> 5, kk = idx & 31;
            As[r][kk] = cvt_tf32(A[(size_t)(rbase+r)*C_ + k0 + kk]);
        }
#pragma unroll
        for (int e = 0; e < 16; e++) {
            int idx = e*256 + t;
            int n = idx >> 5, kk = idx & 31;
            Bs[n][kk] = cvt_tf32(Mo[(size_t)(obase+n)*C_ + k0 + kk] * av[k0+kk]);
        }
        __syncthreads();
#pragma unroll
        for (int ks = 0; ks < 32; ks += 8) {
            uint32_t af[2][4];
#pragma unroll
            for (int i = 0; i < 2; i++) {
                int r = wm*32 + i*16;
                af[i][0] = As[r + lr    ][ks + lc    ];
                af[i][1] = As[r + lr + 8][ks + lc    ];
                af[i][2] = As[r + lr    ][ks + lc + 4];
                af[i][3] = As[r + lr + 8][ks + lc + 4];
            }
#pragma unroll
            for (int j = 0; j < 8; j++) {
                int n = wn*64 + j*8;
                uint32_t b0 = Bs[n + lr][ks + lc    ];
                uint32_t b1 = Bs[n + lr][ks + lc + 4];
#pragma unroll
                for (int i = 0; i < 2; i++) mma_tf32(acc[i][j], af[i], b0, b1);
            }
        }
    }

    const float* bias = g_bias + (size_t)bi*C_;
#pragma unroll
    for (int i = 0; i < 2; i++) {
        int r0 = rbase + wm*32 + i*16 + lr;
        int r1 = r0 + 8;
        int b0r = r0 / S_, s0r = r0 - b0r*S_;
        int b1r = r1 / S_, s1r = r1 - b1r*S_;
#pragma unroll
        for (int j = 0; j < 8; j++) {
            int o = obase + wn*64 + j*8 + 2*lc;
            int h = o >> 6, d = o & 63;
            float bo0 = bias[o], bo1 = bias[o+1];
            float* d0 = g_qkv + ((((size_t)bi*B_ + b0r)*NH_ + h)*S_ + s0r)*HD_ + d;
            d0[0] = acc[i][j][0] + bo0;
            d0[1] = acc[i][j][1] + bo1;
            float* d1 = g_qkv + ((((size_t)bi*B_ + b1r)*NH_ + h)*S_ + s1r)*HD_ + d;
            d1[0] = acc[i][j][2] + bo0;
            d1[1] = acc[i][j][3] + bo1;
        }
    }
}

// ---------------- 6) flash attention on tf32 tensor cores -------------------
__global__ void __launch_bounds__(128) attn_kernel(float* __restrict__ out) {
    __shared__ uint32_t sm_qv[64*68];   // Qs[64][64] swizzled -> Vs[64][68]
    __shared__ uint32_t sm_kp[64*64];   // Ks swizzled -> Ps swizzled

    int t    = threadIdx.x;
    int wid  = t >> 5, lane = t & 31;
    int lr   = lane >> 2, lc = lane & 3;
    int sw   = lr << 2;
    int qt   = blockIdx.x;
    int bh   = blockIdx.y;
    int br   = blockIdx.z;
    int b = bh / NH_, h = bh - b*NH_;

    const float* Qp = g_qkv + (((size_t)(3*br+0)*B_ + b)*NH_ + h)*(size_t)S_*HD_;
    const float* Kp = g_qkv + (((size_t)(3*br+1)*B_ + b)*NH_ + h)*(size_t)S_*HD_;
    const float* Vp = g_qkv + (((size_t)(3*br+2)*B_ + b)*NH_ + h)*(size_t)S_*HD_;
    float* Op = out + ((size_t)br*B_ + b)*(size_t)S_*C_ + (size_t)h*S_*HD_;

    int q0 = qt*64;

#pragma unroll
    for (int e = 0; e < 8; e++) {
        int i4 = e*128 + t;
        int q = i4 >> 4, d0 = (i4 & 15) << 2;
        uint4 v = make_uint4(0u,0u,0u,0u);
        if (q0 + q < S_) {
            float4 f = *(const float4*)&Qp[(size_t)(q0+q)*HD_ + d0];
            v.x = cvt_tf32(f.x); v.y = cvt_tf32(f.y);
            v.z = cvt_tf32(f.z); v.w = cvt_tf32(f.w);
        }
        *(uint4*)&sm_qv[q*64 + (d0 ^ ((q & 7) << 2))] = v;
    }
    __syncthreads();

    int r = wid * 16;
    uint32_t qa[8][4];
#pragma unroll
    for (int ks = 0; ks < 8; ks++) {
        int c0 = 8*ks + lc;
        qa[ks][0] = sm_qv[(r+lr  )*64 + ( c0      ^ sw)];
        qa[ks][1] = sm_qv[(r+lr+8)*64 + ( c0      ^ sw)];
        qa[ks][2] = sm_qv[(r+lr  )*64 + ((c0 + 4) ^ sw)];
        qa[ks][3] = sm_qv[(r+lr+8)*64 + ((c0 + 4) ^ sw)];
    }

    float ov[8][4] = {};
    float m0 = -1e30f, m1 = -1e30f, l0 = 0.f, l1 = 0.f;
    const float scale = 0.05103103630798288f;

    for (int kt = 0; kt < 13; kt++) {
        int k0 = kt*64;
        __syncthreads();

#pragma unroll
        for (int e = 0; e < 8; e++) {
            int i4 = e*128 + t;
            int k = i4 >> 4, d0 = (i4 & 15) << 2;
            uint4 kv = make_uint4(0u,0u,0u,0u);
            uint4 vv = make_uint4(0u,0u,0u,0u);
            if (k0 + k < S_) {
                float4 fk = *(const float4*)&Kp[(size_t)(k0+k)*HD_ + d0];
                float4 fv = *(const float4*)&Vp[(size_t)(k0+k)*HD_ + d0];
                kv.x = cvt_tf32(fk.x); kv.y = cvt_tf32(fk.y);
                kv.z = cvt_tf32(fk.z); kv.w = cvt_tf32(fk.w);
                vv.x = cvt_tf32(fv.x); vv.y = cvt_tf32(fv.y);
                vv.z = cvt_tf32(fv.z); vv.w = cvt_tf32(fv.w);
            }
            *(uint4*)&sm_kp[k*64 + (d0 ^ ((k & 7) << 2))] = kv;
            *(uint4*)&sm_qv[k*68 + d0] = vv;
        }
        __syncthreads();

        float sc[8][4] = {};
#pragma unroll
        for (int ks = 0; ks < 8; ks++) {
            int c0 = 8*ks + lc;
#pragma unroll
            for (int j = 0; j < 8; j++) {
                uint32_t b0 = sm_kp[(8*j+lr)*64 + ( c0      ^ sw)];
                uint32_t b1 = sm_kp[(8*j+lr)*64 + ((c0 + 4) ^ sw)];
                mma_tf32(sc[j], qa[ks], b0, b1);
            }
        }

#pragma unroll
        for (int j = 0; j < 8; j++) {
            int col = k0 + 8*j + 2*lc;
            bool ok0 = col     < S_;
            bool ok1 = col + 1 < S_;
            sc[j][0] = ok0 ? sc[j][0]*scale : -1e30f;
            sc[j][1] = ok1 ? sc[j][1]*scale : -1e30f;
            sc[j][2] = ok0 ? sc[j][2]*scale : -1e30f;
            sc[j][3] = ok1 ? sc[j][3]*scale : -1e30f;
        }

        float mx0 = -1e30f, mx1 = -1e30f;
#pragma unroll
        for (int j = 0; j < 8; j++) {
            mx0 = fmaxf(mx0, fmaxf(sc[j][0], sc[j][1]));
            mx1 = fmaxf(mx1, fmaxf(sc[j][2], sc[j][3]));
        }
        mx0 = fmaxf(mx0, __shfl_xor_sync(0xffffffffu, mx0, 1));
        mx0 = fmaxf(mx0, __shfl_xor_sync(0xffffffffu, mx0, 2));
        mx1 = fmaxf(mx1, __shfl_xor_sync(0xffffffffu, mx1, 1));
        mx1 = fmaxf(mx1, __shfl_xor_sync(0xffffffffu, mx1, 2));
        float mn0 = fmaxf(m0, mx0), mn1 = fmaxf(m1, mx1);
        float a0  = __expf(m0 - mn0), a1 = __expf(m1 - mn1);
        float rs0 = 0.f, rs1 = 0.f;
#pragma unroll
        for (int j = 0; j < 8; j++) {
            sc[j][0] = __expf(sc[j][0] - mn0); rs0 += sc[j][0];
            sc[j][1] = __expf(sc[j][1] - mn0); rs0 += sc[j][1];
            sc[j][2] = __expf(sc[j][2] - mn1); rs1 += sc[j][2];
            sc[j][3] = __expf(sc[j][3] - mn1); rs1 += sc[j][3];
        }
        rs0 += __shfl_xor_sync(0xffffffffu, rs0, 1);
        rs0 += __shfl_xor_sync(0xffffffffu, rs0, 2);
        rs1 += __shfl_xor_sync(0xffffffffu, rs1, 1);
        rs1 += __shfl_xor_sync(0xffffffffu, rs1, 2);
        l0 = l0*a0 + rs0;  l1 = l1*a1 + rs1;
        m0 = mn0;          m1 = mn1;
#pragma unroll
        for (int j = 0; j < 8; j++) {
            ov[j][0] *= a0; ov[j][1] *= a0;
            ov[j][2] *= a1; ov[j][3] *= a1;
        }

        __syncthreads();
#pragma unroll
        for (int j = 0; j < 8; j++) {
            int cc = 8*j + 2*lc;
            uint2 v0; v0.x = cvt_tf32(sc[j][0]); v0.y = cvt_tf32(sc[j][1]);
            *(uint2*)&sm_kp[(r+lr  )*64 + (cc ^ sw)] = v0;
            uint2 v1; v1.x = cvt_tf32(sc[j][2]); v1.y = cvt_tf32(sc[j][3]);
            *(uint2*)&sm_kp[(r+lr+8)*64 + (cc ^ sw)] = v1;
        }
        __syncthreads();

#pragma unroll
        for (int ks = 0; ks < 8; ks++) {
            int c0 = 8*ks + lc;
            uint32_t pa[4];
            pa[0] = sm_kp[(r+lr  )*64 + ( c0      ^ sw)];
            pa[1] = sm_kp[(r+lr+8)*64 + ( c0      ^ sw)];
            pa[2] = sm_kp[(r+lr  )*64 + ((c0 + 4) ^ sw)];
            pa[3] = sm_kp[(r+lr+8)*64 + ((c0 + 4) ^ sw)];
#pragma unroll
            for (int j = 0; j < 8; j++) {
                uint32_t b0 = sm_qv[(8*ks+lc  )*68 + 8*j + lr];
                uint32_t b1 = sm_qv[(8*ks+lc+4)*68 + 8*j + lr];
                mma_tf32(ov[j], pa, b0, b1);
            }
        }
    }

    float inv0 = 1.0f / l0, inv1 = 1.0f / l1;
    int qq0 = q0 + r + lr, qq1 = qq0 + 8;
#pragma unroll
    for (int j = 0; j < 8; j++) {
        int d = 8*j + 2*lc;
        if (qq0 < S_) {
            float2 o2 = make_float2(ov[j][0]*inv0, ov[j][1]*inv0);
            *(float2*)&Op[(size_t)qq0*HD_ + d] = o2;
        }
        if (qq1 < S_) {
            float2 o2 = make_float2(ov[j][2]*inv1, ov[j][3]*inv1);
            *(float2*)&Op[(size_t)qq1*HD_ + d] = o2;
        }
    }
}

// ---------------------------------------------------------------------------
extern "C" void kernel_launch(void* const* d_in, const int* in_sizes, int n_in,
                              void* d_out, int out_size) {
    const float* x1  = (const float*)d_in[0];
    const float* x2  = (const float*)d_in[3];
    const float* dww = (const float*)d_in[6];
    const float* gam = (const float*)d_in[7];
    const float* bet = (const float*)d_in[8];
    const float* pw  = (const float*)d_in[9];
    const float* pwb = (const float*)d_in[10];
    const float* lin = (const float*)d_in[11];
    float* out = (float*)d_out;

    dw_kernel   <<<dim3(16, 16, 9), 384>>>(x1, x2, dww);
    stats_kernel<<<(NBI*C_*32 + 255)/256, 256>>>(gam, bet);
    fold_kernel <<<dim3(6, 6, 9), 256>>>(pw, lin);
    bias_kernel <<<(NBI*C_*32 + 255)/256, 256>>>(lin, pwb);
    gemm_kernel <<<dim3(3, 98, 9), 256>>>();
    attn_kernel <<<dim3(13, 96, 3), 128>>>(out);
}

// round 11
// speedup vs baseline: 2.8618x; 1.6249x over previous
#include <cuda_runtime.h>
#include <math.h>
#include <stdint.h>

#define B_   16
#define C_   384
#define S_   784
#define NH_  6
#define HD_  64
#define NBI  9
#define NPART 256          // 16 batches * 16 spatial tiles
#define NTOK (B_*S_)       // 12544

// ---------------- scratch (static device globals; no allocation) ------------
__device__ unsigned int g_dw  [(size_t)NBI*NTOK*C_]; // [bi][tok][c] tf32 bits of conv out
__device__ unsigned int g_qkv [(size_t)NBI*NTOK*C_]; // [bi][b][h][s][d] tf32 bits
__device__ float        g_M   [NBI*C_*C_];           // combined lin@pw (fp32, for bias)
__device__ unsigned int g_Mt  [NBI*C_*C_];           // tf32 bits of M * a (gemm B operand)
__device__ float        g_psum[NBI*C_*NPART];
__device__ float        g_psq [NBI*C_*NPART];
__device__ float        g_a   [NBI*C_];              // BN scale fold
__device__ float        g_bc  [NBI*C_];              // BN shift fold
__device__ float        g_bias[NBI*C_];              // combined output bias

// ---------------- helpers ---------------------------------------------------
__device__ __forceinline__ uint32_t cvt_tf32(float x) {
    uint32_t r;
    asm("cvt.rna.tf32.f32 %0, %1;" : "=r"(r) : "f"(x));
    return r;
}

__device__ __forceinline__ void mma_tf32(float c[4], const uint32_t a[4],
                                         uint32_t b0, uint32_t b1) {
    asm volatile(
        "mma.sync.aligned.m16n8k8.row.col.f32.tf32.tf32.f32 "
        "{%0,%1,%2,%3}, {%4,%5,%6,%7}, {%8,%9}, {%0,%1,%2,%3};\n"
        : "+f"(c[0]), "+f"(c[1]), "+f"(c[2]), "+f"(c[3])
        : "r"(a[0]), "r"(a[1]), "r"(a[2]), "r"(a[3]), "r"(b0), "r"(b1));
}

__device__ __forceinline__ uint32_t smem_u32(const void* p) {
    uint32_t a;
    asm("{ .reg .u64 t; cvta.to.shared.u64 t, %1; cvt.u32.u64 %0, t; }"
        : "=r"(a) : "l"(p));
    return a;
}

#define CP_A16(dst, src) \
    asm volatile("cp.async.ca.shared.global [%0], [%1], 16;\n" \
                 :: "r"(dst), "l"(src) : "memory")
#define CP_A16P(dst, src, ok) \
    asm volatile("cp.async.ca.shared.global [%0], [%1], 16, %2;\n" \
                 :: "r"(dst), "l"(src), "r"((ok) ? 16 : 0) : "memory")
#define CP_COMMIT() asm volatile("cp.async.commit_group;\n" ::: "memory")
#define CP_WAIT(n)  asm volatile("cp.async.wait_group %0;\n" :: "n"(n) : "memory")

// ---------------- 1) depthwise 3x3 conv + BN partial stats ------------------
__global__ void dw_kernel(const float* __restrict__ x1, const float* __restrict__ x2,
                          const float* __restrict__ dww) {
    int c    = threadIdx.x;        // 0..383
    int tile = blockIdx.x;         // 16 tiles of 49 spatial positions
    int b    = blockIdx.y;
    int bi   = blockIdx.z;
    int br   = bi / 3;

    float w[9];
#pragma unroll
    for (int k = 0; k < 9; k++) w[k] = dww[(bi*C_ + c)*9 + k];

    const float* X1 = x1 + (size_t)b*S_*C_;
    const float* X2 = x2 + (size_t)b*S_*C_;
    unsigned int* out = g_dw + ((size_t)bi*B_ + b)*(size_t)S_*C_;

    float sum = 0.f, sq = 0.f;
    for (int i = 0; i < 49; i++) {
        int s = tile*49 + i;
        int y = s / 28, x = s - y*28;
        float acc = 0.f;
#pragma unroll
        for (int ky = 0; ky < 3; ky++) {
            int yy = y + ky - 1;
            if (yy < 0 || yy >= 28) continue;
#pragma unroll
            for (int kx = 0; kx < 3; kx++) {
                int xx = x + kx - 1;
                if (xx < 0 || xx >= 28) continue;
                int sn = yy*28 + xx;
                float v;
                if      (br == 0) v = X1[sn*C_ + c];
                else if (br == 1) v = X2[sn*C_ + c];
                else              v = X1[sn*C_ + c] + X2[sn*C_ + c];
                acc += w[ky*3+kx] * v;
            }
        }
        out[s*C_ + c] = cvt_tf32(acc);   // gemm A operand, pre-converted
        sum += acc;  sq += acc*acc;      // exact fp32 stats
    }
    int p = b*16 + tile;
    g_psum[(bi*C_ + c)*NPART + p] = sum;
    g_psq [(bi*C_ + c)*NPART + p] = sq;
}

// ---------------- 2) finalize BN stats (warp per channel) -------------------
__global__ void stats_kernel(const float* __restrict__ gamma, const float* __restrict__ beta) {
    int gw   = (blockIdx.x*256 + threadIdx.x) >> 5;
    int lane = threadIdx.x & 31;
    if (gw >= NBI*C_) return;
    const float* ps = g_psum + (size_t)gw*NPART;
    const float* pq = g_psq  + (size_t)gw*NPART;
    double s = 0.0, q = 0.0;
#pragma unroll
    for (int i = 0; i < NPART/32; i++) { s += ps[lane + i*32]; q += pq[lane + i*32]; }
#pragma unroll
    for (int o = 16; o > 0; o >>= 1) {
        s += __shfl_xor_sync(0xffffffffu, s, o);
        q += __shfl_xor_sync(0xffffffffu, q, o);
    }
    if (lane == 0) {
        const double N = (double)(B_*S_);
        float mu  = (float)(s / N);
        float var = (float)(q / N - (s/N)*(s/N));
        float a   = gamma[gw] * rsqrtf(var + 1e-5f);
        g_a [gw] = a;
        g_bc[gw] = beta[gw] - mu*a;
    }
}

// ---------------- 3) fold: M[bi] = lin[li] @ pw[bi]; also M*a as tf32 -------
__global__ void __launch_bounds__(256) fold_kernel(const float* __restrict__ pw,
                                                   const float* __restrict__ lin) {
    int bi = blockIdx.z;
    int br = bi / 3, j = bi - 3*br;
    int li = (br == 2 ? 3 : 3*br) + j;      // branch-3 reuses branch-2 lin weights
    const float* L = lin + (size_t)li*C_*C_;   // [o][j]
    const float* P = pw  + (size_t)bi*C_*C_;   // [j][c]

    __shared__ float As[16][65];
    __shared__ float Bs[16][65];
    int t  = threadIdx.x;
    int tx = t & 15, ty = t >> 4;
    int obase = blockIdx.y*64, cbase = blockIdx.x*64;
    float acc[4][4] = {};

    for (int k0 = 0; k0 < C_; k0 += 16) {
#pragma unroll
        for (int e = 0; e < 4; e++) {
            int idx = t + e*256;
            int kk = idx & 15, oo = idx >> 4;
            As[kk][oo] = L[(obase+oo)*C_ + k0 + kk];
        }
#pragma unroll
        for (int e = 0; e < 4; e++) {
            int cc = t & 63, kk = (t >> 6) + e*4;
            Bs[kk][cc] = P[(k0+kk)*C_ + cbase + cc];
        }
        __syncthreads();
#pragma unroll
        for (int kk = 0; kk < 16; kk++) {
            float ar[4], brr[4];
#pragma unroll
            for (int i = 0; i < 4; i++) ar[i]  = As[kk][ty*4+i];
#pragma unroll
            for (int jj = 0; jj < 4; jj++) brr[jj] = Bs[kk][tx*4+jj];
#pragma unroll
            for (int i = 0; i < 4; i++)
#pragma unroll
                for (int jj = 0; jj < 4; jj++) acc[i][jj] += ar[i]*brr[jj];
        }
        __syncthreads();
    }
    float*        Mo = g_M  + (size_t)bi*C_*C_;
    unsigned int* Mt = g_Mt + (size_t)bi*C_*C_;
#pragma unroll
    for (int i = 0; i < 4; i++)
#pragma unroll
        for (int jj = 0; jj < 4; jj++) {
            int oo = obase + ty*4 + i, cc = cbase + tx*4 + jj;
            Mo[oo*C_ + cc] = acc[i][jj];
            Mt[oo*C_ + cc] = cvt_tf32(acc[i][jj] * g_a[bi*C_ + cc]);
        }
}

// ---------------- 4) combined bias (warp per output) ------------------------
__global__ void bias_kernel(const float* __restrict__ lin, const float* __restrict__ pwb) {
    int gw   = (blockIdx.x*256 + threadIdx.x) >> 5;
    int lane = threadIdx.x & 31;
    if (gw >= NBI*C_) return;
    int bi = gw / C_, o = gw - bi*C_;
    int brr = bi/3, j = bi - 3*brr;
    int li = (brr == 2 ? 3 : 3*brr) + j;
    const float* L    = lin + ((size_t)li*C_ + o)*C_;
    const float* Pb   = pwb + (size_t)bi*C_;
    const float* Mrow = g_M + ((size_t)bi*C_ + o)*C_;
    const float* bc   = g_bc + (size_t)bi*C_;
    float s = 0.f;
    for (int k = lane; k < C_; k += 32) s += L[k]*Pb[k] + Mrow[k]*bc[k];
#pragma unroll
    for (int off = 16; off > 0; off >>= 1) s += __shfl_xor_sync(0xffffffffu, s, off);
    if (lane == 0) g_bias[gw] = s;
}

// ---------------- 5) main GEMM (tf32 tensor cores, cp.async 2-stage) --------
// heads = dw @ (M*a)^T + bias. Block 128x128, BK=32, 256 thr = 8 warps (4x2),
// all operands pre-converted tf32 bits. Dyn smem 73728 B (2 stages A+B).
__global__ void __launch_bounds__(256) gemm_kernel() {
    extern __shared__ uint32_t gsm[];
    // layout (u32 idx): As0 @0, As1 @4608, Bs0 @9216, Bs1 @13824 (pad 36/row)
    uint32_t sb = smem_u32(gsm);

    int bi    = blockIdx.z;
    int rbase = blockIdx.y * 128;
    int obase = blockIdx.x * 128;
    const uint32_t* Ag = g_dw + (size_t)bi*NTOK*C_;
    const uint32_t* Bg = g_Mt + (size_t)bi*C_*C_;

    int t    = threadIdx.x;
    int wid  = t >> 5, lane = t & 31;
    int wm   = wid >> 1, wn = wid & 1;
    int lr   = lane >> 2, lc = lane & 3;

    float acc[2][8][4] = {};

    // prologue: stage 0  (tile rows 128, width 32 u32 -> 8 chunks of 4)
    {
        uint32_t ab = sb, bb = sb + 9216u*4u;
#pragma unroll
        for (int e = 0; e < 4; e++) {
            int i = e*256 + t;
            int r = i >> 3, c4 = (i & 7) << 2;
            CP_A16(ab + (uint32_t)(r*36 + c4)*4u, Ag + (size_t)(rbase+r)*C_ + c4);
            CP_A16(bb + (uint32_t)(r*36 + c4)*4u, Bg + (size_t)(obase+r)*C_ + c4);
        }
        CP_COMMIT();
    }

    for (int kt = 0; kt < 12; kt++) {
        __syncthreads();                         // prev MMA done; next stage free
        if (kt < 11) {
            int k0n = (kt+1)*32;
            uint32_t st = (uint32_t)((kt+1) & 1);
            uint32_t ab = sb + st*4608u*4u;
            uint32_t bb = sb + (9216u + st*4608u)*4u;
#pragma unroll
            for (int e = 0; e < 4; e++) {
                int i = e*256 + t;
                int r = i >> 3, c4 = (i & 7) << 2;
                CP_A16(ab + (uint32_t)(r*36 + c4)*4u, Ag + (size_t)(rbase+r)*C_ + k0n + c4);
                CP_A16(bb + (uint32_t)(r*36 + c4)*4u, Bg + (size_t)(obase+r)*C_ + k0n + c4);
            }
        }
        CP_COMMIT();
        CP_WAIT(1);
        __syncthreads();                         // stage kt ready & visible

        const uint32_t* As = gsm + (kt & 1)*4608;
        const uint32_t* Bs = gsm + 9216 + (kt & 1)*4608;
#pragma unroll
        for (int ks = 0; ks < 32; ks += 8) {
            uint32_t af[2][4];
#pragma unroll
            for (int i = 0; i < 2; i++) {
                int r = wm*32 + i*16;
                af[i][0] = As[(r + lr    )*36 + ks + lc    ];
                af[i][1] = As[(r + lr + 8)*36 + ks + lc    ];
                af[i][2] = As[(r + lr    )*36 + ks + lc + 4];
                af[i][3] = As[(r + lr + 8)*36 + ks + lc + 4];
            }
#pragma unroll
            for (int j = 0; j < 8; j++) {
                int n = wn*64 + j*8;
                uint32_t b0 = Bs[(n + lr)*36 + ks + lc    ];
                uint32_t b1 = Bs[(n + lr)*36 + ks + lc + 4];
#pragma unroll
                for (int i = 0; i < 2; i++) mma_tf32(acc[i][j], af[i], b0, b1);
            }
        }
    }

    // epilogue: write tf32 bits of (acc + bias) into [bi][b][h][s][d]
    const float* bias = g_bias + (size_t)bi*C_;
#pragma unroll
    for (int i = 0; i < 2; i++) {
        int r0 = rbase + wm*32 + i*16 + lr;
        int r1 = r0 + 8;
        int b0r = r0 / S_, s0r = r0 - b0r*S_;
        int b1r = r1 / S_, s1r = r1 - b1r*S_;
#pragma unroll
        for (int j = 0; j < 8; j++) {
            int o = obase + wn*64 + j*8 + 2*lc;
            int h = o >> 6, d = o & 63;
            float bo0 = bias[o], bo1 = bias[o+1];
            unsigned int* d0 = g_qkv + ((((size_t)bi*B_ + b0r)*NH_ + h)*S_ + s0r)*HD_ + d;
            d0[0] = cvt_tf32(acc[i][j][0] + bo0);
            d0[1] = cvt_tf32(acc[i][j][1] + bo1);
            unsigned int* d1 = g_qkv + ((((size_t)bi*B_ + b1r)*NH_ + h)*S_ + s1r)*HD_ + d;
            d1[0] = cvt_tf32(acc[i][j][2] + bo0);
            d1[1] = cvt_tf32(acc[i][j][3] + bo1);
        }
    }
}

// ---------------- 6) flash attention (tf32 mma, cp.async pipeline) ----------
// 128 thr / 4 warps, TQ=64, TK=64. Q/P buffer (swizzled) + 2-stage K (swizzled)
// + V (pad 72, conflict-free transposed B-frag gather). Dyn smem 67584 B.
// Group ledger per iter: [V(kt)][K(kt+1)] -> wait 2 before QK, wait 1 before PV.
// Tiles are 64 u32 wide -> loaders cover 16 chunks/row (e<8, i>>4, i&15).
__global__ void __launch_bounds__(128) attn_kernel(float* __restrict__ out) {
    extern __shared__ uint32_t smem[];
    uint32_t* sm_q = smem;              // 64*64  (Q, then P)
    uint32_t* sm_k = smem + 4096;       // 2 x 64*64
    uint32_t* sm_v = smem + 12288;      // 64*72
    uint32_t sb   = smem_u32(smem);
    uint32_t sb_q = sb;
    uint32_t sb_k = sb + 4096u*4u;
    uint32_t sb_v = sb + 12288u*4u;

    int t    = threadIdx.x;
    int wid  = t >> 5, lane = t & 31;
    int lr   = lane >> 2, lc = lane & 3;
    int sw   = lr << 2;
    int qt   = blockIdx.x;
    int bh   = blockIdx.y;
    int br   = blockIdx.z;
    int b = bh / NH_, h = bh - b*NH_;

    const uint32_t* Qg = g_qkv + (((size_t)(3*br+0)*B_ + b)*NH_ + h)*(size_t)S_*HD_;
    const uint32_t* Kg = g_qkv + (((size_t)(3*br+1)*B_ + b)*NH_ + h)*(size_t)S_*HD_;
    const uint32_t* Vg = g_qkv + (((size_t)(3*br+2)*B_ + b)*NH_ + h)*(size_t)S_*HD_;
    float* Op = out + ((size_t)br*B_ + b)*(size_t)S_*C_ + (size_t)h*S_*HD_;

    int q0 = qt*64;

    // prologue: async Q, then K(0) into stage 0 (full 64-wide rows)
#pragma unroll
    for (int e = 0; e < 8; e++) {
        int i = e*128 + t;
        int q = i >> 4, d0 = (i & 15) << 2;
        int qg = q0 + q;
        const uint32_t* src = Qg + (size_t)(qg < S_ ? qg : S_-1)*HD_ + d0;
        CP_A16P(sb_q + (uint32_t)(q*64 + (d0 ^ ((q&7)<<2)))*4u, src, qg < S_);
    }
    CP_COMMIT();
#pragma unroll
    for (int e = 0; e < 8; e++) {
        int i = e*128 + t;
        int k = i >> 4, d0 = (i & 15) << 2;
        const uint32_t* src = Kg + (size_t)(k < S_ ? k : S_-1)*HD_ + d0;
        CP_A16P(sb_k + (uint32_t)(k*64 + (d0 ^ ((k&7)<<2)))*4u, src, k < S_);
    }
    CP_COMMIT();
    CP_WAIT(1);            // Q ready (K0 may still be in flight)
    __syncthreads();

    // hoist Q A-frags
    int r = wid * 16;
    uint32_t qa[8][4];
#pragma unroll
    for (int ks = 0; ks < 8; ks++) {
        int c0 = 8*ks + lc;
        qa[ks][0] = sm_q[(r+lr  )*64 + ( c0      ^ sw)];
        qa[ks][1] = sm_q[(r+lr+8)*64 + ( c0      ^ sw)];
        qa[ks][2] = sm_q[(r+lr  )*64 + ((c0 + 4) ^ sw)];
        qa[ks][3] = sm_q[(r+lr+8)*64 + ((c0 + 4) ^ sw)];
    }

    float ov[8][4] = {};
    float m0 = -1e30f, m1 = -1e30f, l0 = 0.f, l1 = 0.f;
    const float scale = 0.05103103630798288f;   // 384^-0.5

    for (int kt = 0; kt < 13; kt++) {
        int k0 = kt*64;
        __syncthreads();        // (A) PV(kt-1) done: V free, K[(kt+1)&1] free, P consumed

        // issue V(kt)
#pragma unroll
        for (int e = 0; e < 8; e++) {
            int i = e*128 + t;
            int k = i >> 4, d0 = (i & 15) << 2;
            int kg = k0 + k;
            const uint32_t* src = Vg + (size_t)(kg < S_ ? kg : S_-1)*HD_ + d0;
            CP_A16P(sb_v + (uint32_t)(k*72 + d0)*4u, src, kg < S_);
        }
        CP_COMMIT();
        // issue K(kt+1)
        if (kt < 12) {
            int kn = (kt+1)*64;
            uint32_t kb = sb_k + (uint32_t)((kt+1) & 1)*16384u;
#pragma unroll
            for (int e = 0; e < 8; e++) {
                int i = e*128 + t;
                int k = i >> 4, d0 = (i & 15) << 2;
                int kg = kn + k;
                const uint32_t* src = Kg + (size_t)(kg < S_ ? kg : S_-1)*HD_ + d0;
                CP_A16P(kb + (uint32_t)(k*64 + (d0 ^ ((k&7)<<2)))*4u, src, kg < S_);
            }
        }
        CP_COMMIT();
        CP_WAIT(2);             // K(kt) complete
        __syncthreads();        // (B) K(kt) visible

        const uint32_t* Ks_ = sm_k + (kt & 1)*4096;

        // ---- scores: S[16q x 64k] per warp ----
        float sc[8][4] = {};
#pragma unroll
        for (int ks = 0; ks < 8; ks++) {
            int c0 = 8*ks + lc;
#pragma unroll
            for (int j = 0; j < 8; j++) {
                uint32_t b0 = Ks_[(8*j+lr)*64 + ( c0      ^ sw)];
                uint32_t b1 = Ks_[(8*j+lr)*64 + ((c0 + 4) ^ sw)];
                mma_tf32(sc[j], qa[ks], b0, b1);
            }
        }

#pragma unroll
        for (int j = 0; j < 8; j++) {
            int col = k0 + 8*j + 2*lc;
            bool ok0 = col     < S_;
            bool ok1 = col + 1 < S_;
            sc[j][0] = ok0 ? sc[j][0]*scale : -1e30f;
            sc[j][1] = ok1 ? sc[j][1]*scale : -1e30f;
            sc[j][2] = ok0 ? sc[j][2]*scale : -1e30f;
            sc[j][3] = ok1 ? sc[j][3]*scale : -1e30f;
        }

        // ---- online softmax (rows lr / lr+8; reduce across 4-lane group) ----
        float mx0 = -1e30f, mx1 = -1e30f;
#pragma unroll
        for (int j = 0; j < 8; j++) {
            mx0 = fmaxf(mx0, fmaxf(sc[j][0], sc[j][1]));
            mx1 = fmaxf(mx1, fmaxf(sc[j][2], sc[j][3]));
        }
        mx0 = fmaxf(mx0, __shfl_xor_sync(0xffffffffu, mx0, 1));
        mx0 = fmaxf(mx0, __shfl_xor_sync(0xffffffffu, mx0, 2));
        mx1 = fmaxf(mx1, __shfl_xor_sync(0xffffffffu, mx1, 1));
        mx1 = fmaxf(mx1, __shfl_xor_sync(0xffffffffu, mx1, 2));
        float mn0 = fmaxf(m0, mx0), mn1 = fmaxf(m1, mx1);
        float a0  = __expf(m0 - mn0), a1 = __expf(m1 - mn1);
        float rs0 = 0.f, rs1 = 0.f;
#pragma unroll
        for (int j = 0; j < 8; j++) {
            sc[j][0] = __expf(sc[j][0] - mn0); rs0 += sc[j][0];
            sc[j][1] = __expf(sc[j][1] - mn0); rs0 += sc[j][1];
            sc[j][2] = __expf(sc[j][2] - mn1); rs1 += sc[j][2];
            sc[j][3] = __expf(sc[j][3] - mn1); rs1 += sc[j][3];
        }
        rs0 += __shfl_xor_sync(0xffffffffu, rs0, 1);
        rs0 += __shfl_xor_sync(0xffffffffu, rs0, 2);
        rs1 += __shfl_xor_sync(0xffffffffu, rs1, 1);
        rs1 += __shfl_xor_sync(0xffffffffu, rs1, 2);
        l0 = l0*a0 + rs0;  l1 = l1*a1 + rs1;
        m0 = mn0;          m1 = mn1;
#pragma unroll
        for (int j = 0; j < 8; j++) {
            ov[j][0] *= a0; ov[j][1] *= a0;
            ov[j][2] *= a1; ov[j][3] *= a1;
        }

        // ---- store P into Q buffer (swizzled tf32 bits) ----
#pragma unroll
        for (int j = 0; j < 8; j++) {
            int cc = 8*j + 2*lc;
            uint2 v0; v0.x = cvt_tf32(sc[j][0]); v0.y = cvt_tf32(sc[j][1]);
            *(uint2*)&sm_q[(r+lr  )*64 + (cc ^ sw)] = v0;
            uint2 v1; v1.x = cvt_tf32(sc[j][2]); v1.y = cvt_tf32(sc[j][3]);
            *(uint2*)&sm_q[(r+lr+8)*64 + (cc ^ sw)] = v1;
        }
        CP_WAIT(1);             // V(kt) complete (K(kt+1) may remain)
        __syncthreads();        // (C) P + V visible

        // ---- PV: O[16q x 64d] += P @ V ----
#pragma unroll
        for (int ks = 0; ks < 8; ks++) {
            int c0 = 8*ks + lc;
            uint32_t pa[4];
            pa[0] = sm_q[(r+lr  )*64 + ( c0      ^ sw)];
            pa[1] = sm_q[(r+lr+8)*64 + ( c0      ^ sw)];
            pa[2] = sm_q[(r+lr  )*64 + ((c0 + 4) ^ sw)];
            pa[3] = sm_q[(r+lr+8)*64 + ((c0 + 4) ^ sw)];
#pragma unroll
            for (int j = 0; j < 8; j++) {
                uint32_t b0 = sm_v[(8*ks+lc  )*72 + 8*j + lr];   // pad 72: conflict-free
                uint32_t b1 = sm_v[(8*ks+lc+4)*72 + 8*j + lr];
                mma_tf32(ov[j], pa, b0, b1);
            }
        }
    }

    float inv0 = 1.0f / l0, inv1 = 1.0f / l1;
    int qq0 = q0 + r + lr, qq1 = qq0 + 8;
#pragma unroll
    for (int j = 0; j < 8; j++) {
        int d = 8*j + 2*lc;
        if (qq0 < S_) {
            float2 o2 = make_float2(ov[j][0]*inv0, ov[j][1]*inv0);
            *(float2*)&Op[(size_t)qq0*HD_ + d] = o2;
        }
        if (qq1 < S_) {
            float2 o2 = make_float2(ov[j][2]*inv1, ov[j][3]*inv1);
            *(float2*)&Op[(size_t)qq1*HD_ + d] = o2;
        }
    }
}

// ---------------------------------------------------------------------------
extern "C" void kernel_launch(void* const* d_in, const int* in_sizes, int n_in,
                              void* d_out, int out_size) {
    // metadata order: x1, h1, w1, x2, h2, w2, dw_w, bn_gamma, bn_beta, pw_w, pw_b, lin_w
    const float* x1  = (const float*)d_in[0];
    const float* x2  = (const float*)d_in[3];
    const float* dww = (const float*)d_in[6];
    const float* gam = (const float*)d_in[7];
    const float* bet = (const float*)d_in[8];
    const float* pw  = (const float*)d_in[9];
    const float* pwb = (const float*)d_in[10];
    const float* lin = (const float*)d_in[11];
    float* out = (float*)d_out;

    cudaFuncSetAttribute(gemm_kernel, cudaFuncAttributeMaxDynamicSharedMemorySize, 73728);
    cudaFuncSetAttribute(attn_kernel, cudaFuncAttributeMaxDynamicSharedMemorySize, 67584);

    dw_kernel   <<<dim3(16, 16, 9), 384>>>(x1, x2, dww);
    stats_kernel<<<(NBI*C_*32 + 255)/256, 256>>>(gam, bet);
    fold_kernel <<<dim3(6, 6, 9), 256>>>(pw, lin);
    bias_kernel <<<(NBI*C_*32 + 255)/256, 256>>>(lin, pwb);
    gemm_kernel <<<dim3(3, 98, 9), 256, 73728>>>();
    attn_kernel <<<dim3(13, 96, 3), 128, 67584>>>(out);
}

// round 12
// speedup vs baseline: 2.9292x; 1.0235x over previous
#include <cuda_runtime.h>
#include <math.h>
#include <stdint.h>

#define B_   16
#define C_   384
#define S_   784
#define NH_  6
#define HD_  64
#define NBI  9
#define NPART 256          // 16 batches * 16 spatial tiles
#define NTOK (B_*S_)       // 12544

// ---------------- scratch (static device globals; no allocation) ------------
__device__ unsigned int g_dw  [(size_t)NBI*NTOK*C_]; // [bi][tok][c] tf32 bits of conv out
__device__ unsigned int g_qkv [(size_t)NBI*NTOK*C_]; // [bi][b][h][s][d] tf32 bits (q pre-scaled by scale*log2e)
__device__ float        g_M   [NBI*C_*C_];           // combined lin@pw (fp32, for bias)
__device__ unsigned int g_Mt  [NBI*C_*C_];           // tf32 bits of M * a (gemm B operand)
__device__ float        g_psum[NBI*C_*NPART];
__device__ float        g_psq [NBI*C_*NPART];
__device__ float        g_a   [NBI*C_];              // BN scale fold
__device__ float        g_bc  [NBI*C_];              // BN shift fold
__device__ float        g_bias[NBI*C_];              // combined output bias

// ---------------- helpers ---------------------------------------------------
__device__ __forceinline__ uint32_t cvt_tf32(float x) {
    uint32_t r;
    asm("cvt.rna.tf32.f32 %0, %1;" : "=r"(r) : "f"(x));
    return r;
}

__device__ __forceinline__ float ex2f(float x) {
    float r;
    asm("ex2.approx.f32 %0, %1;" : "=f"(r) : "f"(x));
    return r;
}

__device__ __forceinline__ void mma_tf32(float c[4], const uint32_t a[4],
                                         uint32_t b0, uint32_t b1) {
    asm volatile(
        "mma.sync.aligned.m16n8k8.row.col.f32.tf32.tf32.f32 "
        "{%0,%1,%2,%3}, {%4,%5,%6,%7}, {%8,%9}, {%0,%1,%2,%3};\n"
        : "+f"(c[0]), "+f"(c[1]), "+f"(c[2]), "+f"(c[3])
        : "r"(a[0]), "r"(a[1]), "r"(a[2]), "r"(a[3]), "r"(b0), "r"(b1));
}

__device__ __forceinline__ uint32_t smem_u32(const void* p) {
    uint32_t a;
    asm("{ .reg .u64 t; cvta.to.shared.u64 t, %1; cvt.u32.u64 %0, t; }"
        : "=r"(a) : "l"(p));
    return a;
}

#define CP_A16(dst, src) \
    asm volatile("cp.async.ca.shared.global [%0], [%1], 16;\n" \
                 :: "r"(dst), "l"(src) : "memory")
#define CP_A16P(dst, src, ok) \
    asm volatile("cp.async.ca.shared.global [%0], [%1], 16, %2;\n" \
                 :: "r"(dst), "l"(src), "r"((ok) ? 16 : 0) : "memory")
#define CP_COMMIT() asm volatile("cp.async.commit_group;\n" ::: "memory")
#define CP_WAIT(n)  asm volatile("cp.async.wait_group %0;\n" :: "n"(n) : "memory")

// scale * log2e = 384^-0.5 * 1.4426950408889634
#define QSCALE 0.07362222f

// ---------------- 1) depthwise 3x3 conv (q,k,v fused) + BN partial stats ----
__global__ void dw_kernel(const float* __restrict__ x1, const float* __restrict__ x2,
                          const float* __restrict__ dww) {
    int c    = threadIdx.x;        // 0..383
    int tile = blockIdx.x;         // 16 tiles of 49 spatial positions
    int b    = blockIdx.y;
    int br   = blockIdx.z;         // branch: 0,1,2 (q,k,v fused per branch)

    float w[3][9];
#pragma unroll
    for (int j = 0; j < 3; j++)
#pragma unroll
        for (int k = 0; k < 9; k++)
            w[j][k] = dww[((3*br+j)*C_ + c)*9 + k];

    const float* X1 = x1 + (size_t)b*S_*C_;
    const float* X2 = x2 + (size_t)b*S_*C_;
    unsigned int* out0 = g_dw + ((size_t)(3*br+0)*B_ + b)*(size_t)S_*C_;
    unsigned int* out1 = g_dw + ((size_t)(3*br+1)*B_ + b)*(size_t)S_*C_;
    unsigned int* out2 = g_dw + ((size_t)(3*br+2)*B_ + b)*(size_t)S_*C_;

    float sum[3] = {0.f,0.f,0.f}, sq[3] = {0.f,0.f,0.f};
    int s0 = tile*49;
    int y = s0 / 28, x = s0 - y*28;
    for (int i = 0; i < 49; i++) {
        int s = s0 + i;
        float a0 = 0.f, a1 = 0.f, a2 = 0.f;
#pragma unroll
        for (int ky = 0; ky < 3; ky++) {
            int yy = y + ky - 1;
            if (yy < 0 || yy >= 28) continue;
#pragma unroll
            for (int kx = 0; kx < 3; kx++) {
                int xx = x + kx - 1;
                if (xx < 0 || xx >= 28) continue;
                int sn = yy*28 + xx;
                float v;
                if      (br == 0) v = X1[sn*C_ + c];
                else if (br == 1) v = X2[sn*C_ + c];
                else              v = X1[sn*C_ + c] + X2[sn*C_ + c];
                int kk = ky*3 + kx;
                a0 += w[0][kk]*v;  a1 += w[1][kk]*v;  a2 += w[2][kk]*v;
            }
        }
        out0[s*C_ + c] = cvt_tf32(a0);
        out1[s*C_ + c] = cvt_tf32(a1);
        out2[s*C_ + c] = cvt_tf32(a2);
        sum[0] += a0;  sq[0] += a0*a0;
        sum[1] += a1;  sq[1] += a1*a1;
        sum[2] += a2;  sq[2] += a2*a2;
        if (++x == 28) { x = 0; y++; }
    }
    int p = b*16 + tile;
#pragma unroll
    for (int j = 0; j < 3; j++) {
        int bi = 3*br + j;
        g_psum[(bi*C_ + c)*NPART + p] = sum[j];
        g_psq [(bi*C_ + c)*NPART + p] = sq[j];
    }
}

// ---------------- 2) finalize BN stats (warp per channel) -------------------
__global__ void stats_kernel(const float* __restrict__ gamma, const float* __restrict__ beta) {
    int gw   = (blockIdx.x*256 + threadIdx.x) >> 5;
    int lane = threadIdx.x & 31;
    if (gw >= NBI*C_) return;
    const float* ps = g_psum + (size_t)gw*NPART;
    const float* pq = g_psq  + (size_t)gw*NPART;
    double s = 0.0, q = 0.0;
#pragma unroll
    for (int i = 0; i < NPART/32; i++) { s += ps[lane + i*32]; q += pq[lane + i*32]; }
#pragma unroll
    for (int o = 16; o > 0; o >>= 1) {
        s += __shfl_xor_sync(0xffffffffu, s, o);
        q += __shfl_xor_sync(0xffffffffu, q, o);
    }
    if (lane == 0) {
        const double N = (double)(B_*S_);
        float mu  = (float)(s / N);
        float var = (float)(q / N - (s/N)*(s/N));
        float a   = gamma[gw] * rsqrtf(var + 1e-5f);
        g_a [gw] = a;
        g_bc[gw] = beta[gw] - mu*a;
    }
}

// ---------------- 3) fold: M[bi] = lin[li] @ pw[bi]; also M*a as tf32 -------
__global__ void __launch_bounds__(256) fold_kernel(const float* __restrict__ pw,
                                                   const float* __restrict__ lin) {
    int bi = blockIdx.z;
    int br = bi / 3, j = bi - 3*br;
    int li = (br == 2 ? 3 : 3*br) + j;      // branch-3 reuses branch-2 lin weights
    const float* L = lin + (size_t)li*C_*C_;   // [o][j]
    const float* P = pw  + (size_t)bi*C_*C_;   // [j][c]

    __shared__ float As[16][65];
    __shared__ float Bs[16][65];
    int t  = threadIdx.x;
    int tx = t & 15, ty = t >> 4;
    int obase = blockIdx.y*64, cbase = blockIdx.x*64;
    float acc[4][4] = {};

    for (int k0 = 0; k0 < C_; k0 += 16) {
#pragma unroll
        for (int e = 0; e < 4; e++) {
            int idx = t + e*256;
            int kk = idx & 15, oo = idx >> 4;
            As[kk][oo] = L[(obase+oo)*C_ + k0 + kk];
        }
#pragma unroll
        for (int e = 0; e < 4; e++) {
            int cc = t & 63, kk = (t >> 6) + e*4;
            Bs[kk][cc] = P[(k0+kk)*C_ + cbase + cc];
        }
        __syncthreads();
#pragma unroll
        for (int kk = 0; kk < 16; kk++) {
            float ar[4], brr[4];
#pragma unroll
            for (int i = 0; i < 4; i++) ar[i]  = As[kk][ty*4+i];
#pragma unroll
            for (int jj = 0; jj < 4; jj++) brr[jj] = Bs[kk][tx*4+jj];
#pragma unroll
            for (int i = 0; i < 4; i++)
#pragma unroll
                for (int jj = 0; jj < 4; jj++) acc[i][jj] += ar[i]*brr[jj];
        }
        __syncthreads();
    }
    float*        Mo = g_M  + (size_t)bi*C_*C_;
    unsigned int* Mt = g_Mt + (size_t)bi*C_*C_;
#pragma unroll
    for (int i = 0; i < 4; i++)
#pragma unroll
        for (int jj = 0; jj < 4; jj++) {
            int oo = obase + ty*4 + i, cc = cbase + tx*4 + jj;
            Mo[oo*C_ + cc] = acc[i][jj];
            Mt[oo*C_ + cc] = cvt_tf32(acc[i][jj] * g_a[bi*C_ + cc]);
        }
}

// ---------------- 4) combined bias (warp per output) ------------------------
__global__ void bias_kernel(const float* __restrict__ lin, const float* __restrict__ pwb) {
    int gw   = (blockIdx.x*256 + threadIdx.x) >> 5;
    int lane = threadIdx.x & 31;
    if (gw >= NBI*C_) return;
    int bi = gw / C_, o = gw - bi*C_;
    int brr = bi/3, j = bi - 3*brr;
    int li = (brr == 2 ? 3 : 3*brr) + j;
    const float* L    = lin + ((size_t)li*C_ + o)*C_;
    const float* Pb   = pwb + (size_t)bi*C_;
    const float* Mrow = g_M + ((size_t)bi*C_ + o)*C_;
    const float* bc   = g_bc + (size_t)bi*C_;
    float s = 0.f;
    for (int k = lane; k < C_; k += 32) s += L[k]*Pb[k] + Mrow[k]*bc[k];
#pragma unroll
    for (int off = 16; off > 0; off >>= 1) s += __shfl_xor_sync(0xffffffffu, s, off);
    if (lane == 0) g_bias[gw] = s;
}

// ---------------- 5) main GEMM (tf32 tensor cores, cp.async 2-stage) --------
// heads = dw @ (M*a)^T + bias; q tensors (bi%3==0) pre-scaled by scale*log2e.
__global__ void __launch_bounds__(256) gemm_kernel() {
    extern __shared__ uint32_t gsm[];
    // layout (u32 idx): As0 @0, As1 @4608, Bs0 @9216, Bs1 @13824 (pad 36/row)
    uint32_t sb = smem_u32(gsm);

    int bi    = blockIdx.z;
    int rbase = blockIdx.y * 128;
    int obase = blockIdx.x * 128;
    const uint32_t* Ag = g_dw + (size_t)bi*NTOK*C_;
    const uint32_t* Bg = g_Mt + (size_t)bi*C_*C_;
    float qs = (bi % 3 == 0) ? QSCALE : 1.0f;

    int t    = threadIdx.x;
    int wid  = t >> 5, lane = t & 31;
    int wm   = wid >> 1, wn = wid & 1;
    int lr   = lane >> 2, lc = lane & 3;

    float acc[2][8][4] = {};

    // prologue: stage 0
    {
        uint32_t ab = sb, bb = sb + 9216u*4u;
#pragma unroll
        for (int e = 0; e < 4; e++) {
            int i = e*256 + t;
            int r = i >> 3, c4 = (i & 7) << 2;
            CP_A16(ab + (uint32_t)(r*36 + c4)*4u, Ag + (size_t)(rbase+r)*C_ + c4);
            CP_A16(bb + (uint32_t)(r*36 + c4)*4u, Bg + (size_t)(obase+r)*C_ + c4);
        }
        CP_COMMIT();
    }

    for (int kt = 0; kt < 12; kt++) {
        __syncthreads();                         // prev MMA done; next stage free
        if (kt < 11) {
            int k0n = (kt+1)*32;
            uint32_t st = (uint32_t)((kt+1) & 1);
            uint32_t ab = sb + st*4608u*4u;
            uint32_t bb = sb + (9216u + st*4608u)*4u;
#pragma unroll
            for (int e = 0; e < 4; e++) {
                int i = e*256 + t;
                int r = i >> 3, c4 = (i & 7) << 2;
                CP_A16(ab + (uint32_t)(r*36 + c4)*4u, Ag + (size_t)(rbase+r)*C_ + k0n + c4);
                CP_A16(bb + (uint32_t)(r*36 + c4)*4u, Bg + (size_t)(obase+r)*C_ + k0n + c4);
            }
        }
        CP_COMMIT();
        CP_WAIT(1);
        __syncthreads();                         // stage kt ready & visible

        const uint32_t* As = gsm + (kt & 1)*4608;
        const uint32_t* Bs = gsm + 9216 + (kt & 1)*4608;
#pragma unroll
        for (int ks = 0; ks < 32; ks += 8) {
            uint32_t af[2][4];
#pragma unroll
            for (int i = 0; i < 2; i++) {
                int r = wm*32 + i*16;
                af[i][0] = As[(r + lr    )*36 + ks + lc    ];
                af[i][1] = As[(r + lr + 8)*36 + ks + lc    ];
                af[i][2] = As[(r + lr    )*36 + ks + lc + 4];
                af[i][3] = As[(r + lr + 8)*36 + ks + lc + 4];
            }
#pragma unroll
            for (int j = 0; j < 8; j++) {
                int n = wn*64 + j*8;
                uint32_t b0 = Bs[(n + lr)*36 + ks + lc    ];
                uint32_t b1 = Bs[(n + lr)*36 + ks + lc + 4];
#pragma unroll
                for (int i = 0; i < 2; i++) mma_tf32(acc[i][j], af[i], b0, b1);
            }
        }
    }

    // epilogue: write tf32 bits of (acc + bias)*qs into [bi][b][h][s][d]
    const float* bias = g_bias + (size_t)bi*C_;
#pragma unroll
    for (int i = 0; i < 2; i++) {
        int r0 = rbase + wm*32 + i*16 + lr;
        int r1 = r0 + 8;
        int b0r = r0 / S_, s0r = r0 - b0r*S_;
        int b1r = r1 / S_, s1r = r1 - b1r*S_;
#pragma unroll
        for (int j = 0; j < 8; j++) {
            int o = obase + wn*64 + j*8 + 2*lc;
            int h = o >> 6, d = o & 63;
            float bo0 = bias[o], bo1 = bias[o+1];
            unsigned int* d0 = g_qkv + ((((size_t)bi*B_ + b0r)*NH_ + h)*S_ + s0r)*HD_ + d;
            d0[0] = cvt_tf32((acc[i][j][0] + bo0) * qs);
            d0[1] = cvt_tf32((acc[i][j][1] + bo1) * qs);
            unsigned int* d1 = g_qkv + ((((size_t)bi*B_ + b1r)*NH_ + h)*S_ + s1r)*HD_ + d;
            d1[0] = cvt_tf32((acc[i][j][2] + bo0) * qs);
            d1[1] = cvt_tf32((acc[i][j][3] + bo1) * qs);
        }
    }
}

// ---------------- 6) flash attention (tf32 mma, cp.async pipeline) ----------
// 256 thr / 8 warps, TQ=128, TK=64. Q/P buffer 128x64 (swizzled) + 2-stage K
// (swizzled) + V (pad 72). Dyn smem 83968 B -> 2 blocks/SM, 16 warps/SM.
// q pre-scaled by scale*log2e -> softmax in log2 domain via ex2.approx.
// Masking only on last k-tile (kt==12). Per-warp code identical to TQ=64 ver.
__global__ void __launch_bounds__(256, 2) attn_kernel(float* __restrict__ out) {
    extern __shared__ uint32_t smem[];
    uint32_t* sm_q = smem;               // 128*64 (Q, then P)
    uint32_t* sm_k = smem + 8192;        // 2 x 64*64
    uint32_t* sm_v = smem + 16384;       // 64*72
    uint32_t sb   = smem_u32(smem);
    uint32_t sb_q = sb;
    uint32_t sb_k = sb + 8192u*4u;
    uint32_t sb_v = sb + 16384u*4u;

    int t    = threadIdx.x;
    int wid  = t >> 5, lane = t & 31;
    int lr   = lane >> 2, lc = lane & 3;
    int sw   = lr << 2;
    int qt   = blockIdx.x;               // 7 q-tiles of 128
    int bh   = blockIdx.y;
    int br   = blockIdx.z;
    int b = bh / NH_, h = bh - b*NH_;

    const uint32_t* Qg = g_qkv + (((size_t)(3*br+0)*B_ + b)*NH_ + h)*(size_t)S_*HD_;
    const uint32_t* Kg = g_qkv + (((size_t)(3*br+1)*B_ + b)*NH_ + h)*(size_t)S_*HD_;
    const uint32_t* Vg = g_qkv + (((size_t)(3*br+2)*B_ + b)*NH_ + h)*(size_t)S_*HD_;
    float* Op = out + ((size_t)br*B_ + b)*(size_t)S_*C_ + (size_t)h*S_*HD_;

    int q0 = qt*128;

    // prologue: async Q (128 rows x 16 chunks), then K(0)
#pragma unroll
    for (int e = 0; e < 8; e++) {
        int i = e*256 + t;
        int q = i >> 4, d0 = (i & 15) << 2;
        int qg = q0 + q;
        const uint32_t* src = Qg + (size_t)(qg < S_ ? qg : S_-1)*HD_ + d0;
        CP_A16P(sb_q + (uint32_t)(q*64 + (d0 ^ ((q&7)<<2)))*4u, src, qg < S_);
    }
    CP_COMMIT();
#pragma unroll
    for (int e = 0; e < 4; e++) {
        int i = e*256 + t;
        int k = i >> 4, d0 = (i & 15) << 2;
        CP_A16(sb_k + (uint32_t)(k*64 + (d0 ^ ((k&7)<<2)))*4u, Kg + (size_t)k*HD_ + d0);
    }
    CP_COMMIT();
    CP_WAIT(1);            // Q ready (K0 may still be in flight)
    __syncthreads();

    // hoist Q A-frags (warp w owns rows 16w..16w+15)
    int r = wid * 16;
    uint32_t qa[8][4];
#pragma unroll
    for (int ks = 0; ks < 8; ks++) {
        int c0 = 8*ks + lc;
        qa[ks][0] = sm_q[(r+lr  )*64 + ( c0      ^ sw)];
        qa[ks][1] = sm_q[(r+lr+8)*64 + ( c0      ^ sw)];
        qa[ks][2] = sm_q[(r+lr  )*64 + ((c0 + 4) ^ sw)];
        qa[ks][3] = sm_q[(r+lr+8)*64 + ((c0 + 4) ^ sw)];
    }

    float ov[8][4] = {};
    float m0 = -1e30f, m1 = -1e30f, l0 = 0.f, l1 = 0.f;

    for (int kt = 0; kt < 13; kt++) {
        int k0 = kt*64;
        __syncthreads();        // (A) PV(kt-1) done: V free, K[(kt+1)&1] free, P consumed

        // issue V(kt)
#pragma unroll
        for (int e = 0; e < 4; e++) {
            int i = e*256 + t;
            int k = i >> 4, d0 = (i & 15) << 2;
            int kg = k0 + k;
            const uint32_t* src = Vg + (size_t)(kg < S_ ? kg : S_-1)*HD_ + d0;
            CP_A16P(sb_v + (uint32_t)(k*72 + d0)*4u, src, kg < S_);
        }
        CP_COMMIT();
        // issue K(kt+1)
        if (kt < 12) {
            int kn = (kt+1)*64;
            uint32_t kb = sb_k + (uint32_t)((kt+1) & 1)*16384u;
#pragma unroll
            for (int e = 0; e < 4; e++) {
                int i = e*256 + t;
                int k = i >> 4, d0 = (i & 15) << 2;
                int kg = kn + k;
                const uint32_t* src = Kg + (size_t)(kg < S_ ? kg : S_-1)*HD_ + d0;
                CP_A16P(kb + (uint32_t)(k*64 + (d0 ^ ((k&7)<<2)))*4u, src, kg < S_);
            }
        }
        CP_COMMIT();
        CP_WAIT(2);             // K(kt) complete
        __syncthreads();        // (B) K(kt) visible

        const uint32_t* Ks_ = sm_k + (kt & 1)*4096;

        // ---- scores: S[16q x 64k] per warp (already in log2 units) ----
        float sc[8][4] = {};
#pragma unroll
        for (int ks = 0; ks < 8; ks++) {
            int c0 = 8*ks + lc;
#pragma unroll
            for (int j = 0; j < 8; j++) {
                uint32_t b0 = Ks_[(8*j+lr)*64 + ( c0      ^ sw)];
                uint32_t b1 = Ks_[(8*j+lr)*64 + ((c0 + 4) ^ sw)];
                mma_tf32(sc[j], qa[ks], b0, b1);
            }
        }

        // ---- masking: only the last k-tile has invalid columns ----
        if (kt == 12) {
#pragma unroll
            for (int j = 0; j < 8; j++) {
                int col = 768 + 8*j + 2*lc;
                if (col     >= S_) { sc[j][0] = -1e30f; sc[j][2] = -1e30f; }
                if (col + 1 >= S_) { sc[j][1] = -1e30f; sc[j][3] = -1e30f; }
            }
        }

        // ---- online softmax, log2 domain (rows lr / lr+8) ----
        float mx0 = -1e30f, mx1 = -1e30f;
#pragma unroll
        for (int j = 0; j < 8; j++) {
            mx0 = fmaxf(mx0, fmaxf(sc[j][0], sc[j][1]));
            mx1 = fmaxf(mx1, fmaxf(sc[j][2], sc[j][3]));
        }
        mx0 = fmaxf(mx0, __shfl_xor_sync(0xffffffffu, mx0, 1));
        mx0 = fmaxf(mx0, __shfl_xor_sync(0xffffffffu, mx0, 2));
        mx1 = fmaxf(mx1, __shfl_xor_sync(0xffffffffu, mx1, 1));
        mx1 = fmaxf(mx1, __shfl_xor_sync(0xffffffffu, mx1, 2));
        float mn0 = fmaxf(m0, mx0), mn1 = fmaxf(m1, mx1);
        float a0  = ex2f(m0 - mn0), a1 = ex2f(m1 - mn1);
        float rs0 = 0.f, rs1 = 0.f;
#pragma unroll
        for (int j = 0; j < 8; j++) {
            sc[j][0] = ex2f(sc[j][0] - mn0); rs0 += sc[j][0];
            sc[j][1] = ex2f(sc[j][1] - mn0); rs0 += sc[j][1];
            sc[j][2] = ex2f(sc[j][2] - mn1); rs1 += sc[j][2];
            sc[j][3] = ex2f(sc[j][3] - mn1); rs1 += sc[j][3];
        }
        rs0 += __shfl_xor_sync(0xffffffffu, rs0, 1);
        rs0 += __shfl_xor_sync(0xffffffffu, rs0, 2);
        rs1 += __shfl_xor_sync(0xffffffffu, rs1, 1);
        rs1 += __shfl_xor_sync(0xffffffffu, rs1, 2);
        l0 = l0*a0 + rs0;  l1 = l1*a1 + rs1;
        m0 = mn0;          m1 = mn1;
#pragma unroll
        for (int j = 0; j < 8; j++) {
            ov[j][0] *= a0; ov[j][1] *= a0;
            ov[j][2] *= a1; ov[j][3] *= a1;
        }

        // ---- store P into Q buffer (swizzled tf32 bits) ----
#pragma unroll
        for (int j = 0; j < 8; j++) {
            int cc = 8*j + 2*lc;
            uint2 v0; v0.x = cvt_tf32(sc[j][0]); v0.y = cvt_tf32(sc[j][1]);
            *(uint2*)&sm_q[(r+lr  )*64 + (cc ^ sw)] = v0;
            uint2 v1; v1.x = cvt_tf32(sc[j][2]); v1.y = cvt_tf32(sc[j][3]);
            *(uint2*)&sm_q[(r+lr+8)*64 + (cc ^ sw)] = v1;
        }
        CP_WAIT(1);             // V(kt) complete (K(kt+1) may remain)
        __syncthreads();        // (C) P + V visible

        // ---- PV: O[16q x 64d] += P @ V ----
#pragma unroll
        for (int ks = 0; ks < 8; ks++) {
            int c0 = 8*ks + lc;
            uint32_t pa[4];
            pa[0] = sm_q[(r+lr  )*64 + ( c0      ^ sw)];
            pa[1] = sm_q[(r+lr+8)*64 + ( c0      ^ sw)];
            pa[2] = sm_q[(r+lr  )*64 + ((c0 + 4) ^ sw)];
            pa[3] = sm_q[(r+lr+8)*64 + ((c0 + 4) ^ sw)];
#pragma unroll
            for (int j = 0; j < 8; j++) {
                uint32_t b0 = sm_v[(8*ks+lc  )*72 + 8*j + lr];   // pad 72: conflict-free
                uint32_t b1 = sm_v[(8*ks+lc+4)*72 + 8*j + lr];
                mma_tf32(ov[j], pa, b0, b1);
            }
        }
    }

    float inv0 = 1.0f / l0, inv1 = 1.0f / l1;
    int qq0 = q0 + r + lr, qq1 = qq0 + 8;
#pragma unroll
    for (int j = 0; j < 8; j++) {
        int d = 8*j + 2*lc;
        if (qq0 < S_) {
            float2 o2 = make_float2(ov[j][0]*inv0, ov[j][1]*inv0);
            *(float2*)&Op[(size_t)qq0*HD_ + d] = o2;
        }
        if (qq1 < S_) {
            float2 o2 = make_float2(ov[j][2]*inv1, ov[j][3]*inv1);
            *(float2*)&Op[(size_t)qq1*HD_ + d] = o2;
        }
    }
}

// ---------------------------------------------------------------------------
extern "C" void kernel_launch(void* const* d_in, const int* in_sizes, int n_in,
                              void* d_out, int out_size) {
    // metadata order: x1, h1, w1, x2, h2, w2, dw_w, bn_gamma, bn_beta, pw_w, pw_b, lin_w
    const float* x1  = (const float*)d_in[0];
    const float* x2  = (const float*)d_in[3];
    const float* dww = (const float*)d_in[6];
    const float* gam = (const float*)d_in[7];
    const float* bet = (const float*)d_in[8];
    const float* pw  = (const float*)d_in[9];
    const float* pwb = (const float*)d_in[10];
    const float* lin = (const float*)d_in[11];
    float* out = (float*)d_out;

    cudaFuncSetAttribute(gemm_kernel, cudaFuncAttributeMaxDynamicSharedMemorySize, 73728);
    cudaFuncSetAttribute(attn_kernel, cudaFuncAttributeMaxDynamicSharedMemorySize, 83968);

    dw_kernel   <<<dim3(16, 16, 3), 384>>>(x1, x2, dww);
    stats_kernel<<<(NBI*C_*32 + 255)/256, 256>>>(gam, bet);
    fold_kernel <<<dim3(6, 6, 9), 256>>>(pw, lin);
    bias_kernel <<<(NBI*C_*32 + 255)/256, 256>>>(lin, pwb);
    gemm_kernel <<<dim3(3, 98, 9), 256, 73728>>>();
    attn_kernel <<<dim3(7, 96, 3), 256, 83968>>>(out);
}